// round 1
// baseline (speedup 1.0000x reference)
#include <cuda_runtime.h>
#include <math.h>

#define B_      8
#define NSEQ    8192
#define DIM     256
#define NQKV    768
#define HEADS   8
#define DH      32
#define NROWS   (B_*NSEQ)          // 65536
#define SCALE_  0.0625f
#define SEGS    16
#define SEGROWS (NSEQ/SEGS)        // 512
#define LN_EPS  1e-5f

// ---------------- scratch (device globals; no dynamic allocation) ------------
__device__ float g_qkv[(size_t)NROWS * NQKV];                 // 192 MB
__device__ float g_Apart[B_*HEADS*SEGS*DH*DH];                // 4 MB
__device__ float g_Spart[B_*HEADS*SEGS*DH];
__device__ float g_A[B_*HEADS*DH*DH];

// ============================================================================
// Kernel 1: qkv = x @ Wqkv.  M=65536, N=768, K=256.
// 128x128 tile, BK=8, 256 threads, 8x8 per thread.
// ============================================================================
__global__ __launch_bounds__(256) void k_qkv_gemm(const float* __restrict__ x,
                                                  const float* __restrict__ W) {
    __shared__ float As[8][129];   // [k][m], padded
    __shared__ float Bs[8][128];   // [k][n]
    int tid = threadIdx.x;
    int row0 = blockIdx.x * 128;
    int col0 = blockIdx.y * 128;
    int tx = tid & 15, ty = tid >> 4;

    // x-tile loader: thread -> row lr, 4 floats at lk
    int lr = tid >> 1;
    int lk = (tid & 1) * 4;
    // W-tile loader: thread -> row wk, 4 floats at wc
    int wk = tid >> 5;
    int wc = (tid & 31) * 4;

    float acc[8][8];
    #pragma unroll
    for (int i = 0; i < 8; i++)
        #pragma unroll
        for (int j = 0; j < 8; j++) acc[i][j] = 0.f;

    for (int k0 = 0; k0 < DIM; k0 += 8) {
        float4 xa = *(const float4*)(x + (size_t)(row0 + lr) * DIM + k0 + lk);
        float4 wa = *(const float4*)(W + (size_t)(k0 + wk) * NQKV + col0 + wc);
        __syncthreads();
        As[lk + 0][lr] = xa.x; As[lk + 1][lr] = xa.y;
        As[lk + 2][lr] = xa.z; As[lk + 3][lr] = xa.w;
        *(float4*)&Bs[wk][wc] = wa;
        __syncthreads();
        #pragma unroll
        for (int kk = 0; kk < 8; kk++) {
            float a[8], b[8];
            #pragma unroll
            for (int i = 0; i < 8; i++) a[i] = As[kk][ty * 8 + i];
            #pragma unroll
            for (int j = 0; j < 8; j++) b[j] = Bs[kk][tx + 16 * j];
            #pragma unroll
            for (int i = 0; i < 8; i++)
                #pragma unroll
                for (int j = 0; j < 8; j++) acc[i][j] += a[i] * b[j];
        }
    }
    #pragma unroll
    for (int i = 0; i < 8; i++) {
        size_t r = (size_t)(row0 + ty * 8 + i) * NQKV + col0;
        #pragma unroll
        for (int j = 0; j < 8; j++)
            g_qkv[r + tx + 16 * j] = acc[i][j];
    }
}

// ============================================================================
// Kernel 2: per (b,h,seg): partial sum of exp(k) per column d, and partial
// Atilde[d][e] = sum_i exp(k[i,d]) * q[i,e].   grid (64, SEGS), 256 threads.
// ============================================================================
__global__ __launch_bounds__(256) void k_stats_partA() {
    int bh  = blockIdx.x;
    int b   = bh >> 3;
    int h   = bh & 7;
    int seg = blockIdx.y;
    int tid  = threadIdx.x;
    int warp = tid >> 5, lane = tid & 31;

    __shared__ __align__(16) float ksh[8][DH];
    __shared__ __align__(16) float qsh[8][DH];
    __shared__ float ssum[8][DH];

    const float* base = g_qkv + (size_t)(b * NSEQ + seg * SEGROWS) * NQKV;
    int kcol = 256 + h * DH + lane;
    int qcol = h * DH + lane;

    int d  = tid >> 3;          // 0..31
    int e0 = (tid & 7) * 4;     // 0,4,...,28
    float acc[4] = {0.f, 0.f, 0.f, 0.f};
    float mysum = 0.f;

    for (int r0 = 0; r0 < SEGROWS; r0 += 8) {
        const float* rowp = base + (size_t)(r0 + warp) * NQKV;
        float kv = expf(rowp[kcol]);
        float qv = rowp[qcol];
        mysum += kv;
        __syncthreads();
        ksh[warp][lane] = kv;
        qsh[warp][lane] = qv;
        __syncthreads();
        #pragma unroll
        for (int r = 0; r < 8; r++) {
            float kd = ksh[r][d];
            float4 q4 = *(const float4*)&qsh[r][e0];
            acc[0] += kd * q4.x; acc[1] += kd * q4.y;
            acc[2] += kd * q4.z; acc[3] += kd * q4.w;
        }
    }
    ssum[warp][lane] = mysum;
    __syncthreads();
    if (warp == 0) {
        float s = 0.f;
        #pragma unroll
        for (int w = 0; w < 8; w++) s += ssum[w][lane];
        g_Spart[(bh * SEGS + seg) * DH + lane] = s;
    }
    float* ap = g_Apart + (size_t)(bh * SEGS + seg) * DH * DH;
    #pragma unroll
    for (int j = 0; j < 4; j++) ap[d * DH + e0 + j] = acc[j];
}

// ============================================================================
// Kernel 3: combine segments -> A[bh][d][e] = SCALE * sum(Atilde)/sum(exp(k)_d)
// ============================================================================
__global__ __launch_bounds__(256) void k_combineA() {
    int bh = blockIdx.x;
    int tid = threadIdx.x;
    __shared__ float sinv[DH];
    if (tid < DH) {
        float s = 0.f;
        for (int seg = 0; seg < SEGS; seg++)
            s += g_Spart[(bh * SEGS + seg) * DH + tid];
        sinv[tid] = SCALE_ / s;
    }
    __syncthreads();
    for (int idx = tid; idx < DH * DH; idx += 256) {
        float a = 0.f;
        for (int seg = 0; seg < SEGS; seg++)
            a += g_Apart[(size_t)(bh * SEGS + seg) * DH * DH + idx];
        g_A[bh * DH * DH + idx] = a * sinv[idx >> 5];
    }
}

// ============================================================================
// Kernel 4: fused  U = v @ A  (with torch-reshape scramble),  Y = U@Wout + b,
// LayerNorm(Y).  One block = 64 output rows (same b,h). 256 threads.
// Dynamic smem: A_sh[1024] | u_sh[64*260] | w_sh[32*256]
// ============================================================================
#define U_STRIDE 260
__global__ __launch_bounds__(256) void k_output(const float* __restrict__ Wout,
                                                const float* __restrict__ bout,
                                                const float* __restrict__ gamma,
                                                const float* __restrict__ beta,
                                                float* __restrict__ out) {
    extern __shared__ float smem[];
    float* A_sh = smem;                       // 1024
    float* u_sh = smem + 1024;                // 64*260
    float* w_sh = u_sh + 64 * U_STRIDE;       // 32*256

    int tid = threadIdx.x;
    int b   = blockIdx.x >> 7;                // 128 blocks per batch
    int tb0 = (blockIdx.x & 127) * 64;        // first output row within batch
    int h   = tb0 >> 10;
    int j0  = (tb0 & 1023) * 8;               // first v row
    int bh  = b * 8 + h;

    // load A (32x32)
    for (int i = tid; i < DH * DH; i += 256) A_sh[i] = g_A[bh * DH * DH + i];
    __syncthreads();

    // phase 1: U512[jl][e] = sum_d v[j0+jl][d] * A[d][e]   (512 rows, 2 passes)
    #pragma unroll
    for (int pass = 0; pass < 2; pass++) {
        int jl = pass * 256 + tid;
        const float* vp = g_qkv + (size_t)(b * NSEQ + j0 + jl) * NQKV + 512 + h * DH;
        float v[32];
        #pragma unroll
        for (int d4 = 0; d4 < 8; d4++) {
            float4 t4 = *(const float4*)(vp + d4 * 4);
            v[d4 * 4 + 0] = t4.x; v[d4 * 4 + 1] = t4.y;
            v[d4 * 4 + 2] = t4.z; v[d4 * 4 + 3] = t4.w;
        }
        float uacc[32];
        #pragma unroll
        for (int e = 0; e < 32; e++) uacc[e] = 0.f;
        #pragma unroll
        for (int d = 0; d < 32; d++) {
            float vd = v[d];
            #pragma unroll
            for (int e = 0; e < 32; e++) uacc[e] += vd * A_sh[d * 32 + e];
        }
        // U[64][256] row-major == U512 row-major; pad rows of 256 to 260
        float* up = u_sh + (jl >> 3) * U_STRIDE + (jl & 7) * 32;
        #pragma unroll
        for (int e = 0; e < 32; e++) up[e] = uacc[e];
    }
    __syncthreads();

    // phase 2: Y[64][256] = U @ Wout ; thread (ty,tx): rows ty*4+i, cols tx+16j
    int tx = tid & 15, ty = tid >> 4;
    float acc2[4][16];
    #pragma unroll
    for (int i = 0; i < 4; i++)
        #pragma unroll
        for (int j = 0; j < 16; j++) acc2[i][j] = 0.f;

    for (int k0 = 0; k0 < 256; k0 += 32) {
        __syncthreads();
        // stage 32x256 chunk of Wout
        for (int l = tid * 4; l < 32 * 256; l += 1024) {
            int kk = l >> 8; int c = l & 255;
            *(float4*)&w_sh[l] = *(const float4*)(Wout + (size_t)(k0 + kk) * 256 + c);
        }
        __syncthreads();
        #pragma unroll
        for (int kk = 0; kk < 32; kk++) {
            float a[4], bf[16];
            #pragma unroll
            for (int i = 0; i < 4; i++) a[i] = u_sh[(ty * 4 + i) * U_STRIDE + k0 + kk];
            #pragma unroll
            for (int j = 0; j < 16; j++) bf[j] = w_sh[kk * 256 + tx + 16 * j];
            #pragma unroll
            for (int i = 0; i < 4; i++)
                #pragma unroll
                for (int j = 0; j < 16; j++) acc2[i][j] += a[i] * bf[j];
        }
    }
    __syncthreads();
    // write Y (+bias) back into u_sh (reuse), same padded layout
    #pragma unroll
    for (int i = 0; i < 4; i++) {
        int r = ty * 4 + i;
        #pragma unroll
        for (int j = 0; j < 16; j++) {
            int c = tx + 16 * j;
            u_sh[r * U_STRIDE + c] = acc2[i][j] + bout[c];
        }
    }
    __syncthreads();

    // LayerNorm: warp w handles rows w*8 .. w*8+7
    int warp = tid >> 5, lane = tid & 31;
    for (int rr = 0; rr < 8; rr++) {
        int r = warp * 8 + rr;
        float vals[8];
        float s = 0.f, s2 = 0.f;
        #pragma unroll
        for (int m = 0; m < 8; m++) {
            float vv = u_sh[r * U_STRIDE + lane + 32 * m];
            vals[m] = vv; s += vv; s2 += vv * vv;
        }
        #pragma unroll
        for (int off = 16; off; off >>= 1) {
            s  += __shfl_xor_sync(0xffffffffu, s,  off);
            s2 += __shfl_xor_sync(0xffffffffu, s2, off);
        }
        float mu  = s * (1.f / 256.f);
        float var = s2 * (1.f / 256.f) - mu * mu;
        float rstd = rsqrtf(var + LN_EPS);
        float* op = out + (size_t)(b * NSEQ + tb0 + r) * 256;
        #pragma unroll
        for (int m = 0; m < 8; m++) {
            int c = lane + 32 * m;
            op[c] = (vals[m] - mu) * rstd * gamma[c] + beta[c];
        }
    }
}

// ============================================================================
extern "C" void kernel_launch(void* const* d_in, const int* in_sizes, int n_in,
                              void* d_out, int out_size) {
    const float* x     = (const float*)d_in[0];
    const float* Wqkv  = (const float*)d_in[1];
    const float* Wout  = (const float*)d_in[2];
    const float* bout  = (const float*)d_in[3];
    const float* gamma = (const float*)d_in[4];
    const float* beta  = (const float*)d_in[5];
    float* out = (float*)d_out;

    k_qkv_gemm<<<dim3(NROWS / 128, NQKV / 128), 256>>>(x, Wqkv);
    k_stats_partA<<<dim3(B_ * HEADS, SEGS), 256>>>();
    k_combineA<<<B_ * HEADS, 256>>>();

    const int smem4 = (1024 + 64 * U_STRIDE + 32 * 256) * (int)sizeof(float);
    cudaFuncSetAttribute(k_output, cudaFuncAttributeMaxDynamicSharedMemorySize, smem4);
    k_output<<<NROWS / 64, 256, smem4>>>(Wout, bout, gamma, beta, out);
}

// round 2
// speedup vs baseline: 2.5971x; 2.5971x over previous
#include <cuda_runtime.h>
#include <cuda_bf16.h>
#include <math.h>
#include <stdint.h>

#define B_      8
#define NSEQ    8192
#define NROWS   65536
#define SCALE_  0.0625f
#define SEGS    16
#define SEGROWS 512
#define LN_EPS  1e-5f

// ---------------- scratch ----------------------------------------------------
__device__ float         g_qk[(size_t)NROWS * 512];          // q (0..255), k (256..511) fp32
__device__ __nv_bfloat16 g_xhi[(size_t)NROWS * 256];
__device__ __nv_bfloat16 g_xlo[(size_t)NROWS * 256];
__device__ __nv_bfloat16 g_whi[256 * 768];
__device__ __nv_bfloat16 g_wlo[256 * 768];
__device__ __nv_bfloat16 g_vhi[(size_t)NROWS * 256];
__device__ __nv_bfloat16 g_vlo[(size_t)NROWS * 256];
__device__ float g_Apart[64 * SEGS * 32 * 32];
__device__ float g_Spart[64 * SEGS * 32];
__device__ float g_A[64 * 32 * 32];
__device__ __nv_bfloat16 g_w2hi[64 * 256 * 256];
__device__ __nv_bfloat16 g_w2lo[64 * 256 * 256];

// ---------------- PTX helpers ------------------------------------------------
__device__ __forceinline__ uint32_t smem_u32(const void* p) {
    return (uint32_t)__cvta_generic_to_shared(p);
}
__device__ __forceinline__ void cp16(void* dst, const void* src) {
    asm volatile("cp.async.cg.shared.global [%0], [%1], 16;\n"
                 :: "r"(smem_u32(dst)), "l"(src));
}
__device__ __forceinline__ void cp_commit() { asm volatile("cp.async.commit_group;\n"); }
template<int N> __device__ __forceinline__ void cp_wait() {
    asm volatile("cp.async.wait_group %0;\n" :: "n"(N));
}
__device__ __forceinline__ void ldsm4(uint32_t (&r)[4], const void* p) {
    asm volatile("ldmatrix.sync.aligned.m8n8.x4.shared.b16 {%0,%1,%2,%3}, [%4];"
                 : "=r"(r[0]), "=r"(r[1]), "=r"(r[2]), "=r"(r[3]) : "r"(smem_u32(p)));
}
__device__ __forceinline__ void ldsm4t(uint32_t (&r)[4], const void* p) {
    asm volatile("ldmatrix.sync.aligned.m8n8.x4.trans.shared.b16 {%0,%1,%2,%3}, [%4];"
                 : "=r"(r[0]), "=r"(r[1]), "=r"(r[2]), "=r"(r[3]) : "r"(smem_u32(p)));
}
__device__ __forceinline__ void mma16816(float (&d)[4], const uint32_t (&a)[4], const uint32_t* b) {
    asm volatile("mma.sync.aligned.m16n8k16.row.col.f32.bf16.bf16.f32 "
                 "{%0,%1,%2,%3}, {%4,%5,%6,%7}, {%8,%9}, {%0,%1,%2,%3};"
                 : "+f"(d[0]), "+f"(d[1]), "+f"(d[2]), "+f"(d[3])
                 : "r"(a[0]), "r"(a[1]), "r"(a[2]), "r"(a[3]), "r"(b[0]), "r"(b[1]));
}
__device__ __forceinline__ void split_bf(float v, __nv_bfloat16& hi, __nv_bfloat16& lo) {
    hi = __float2bfloat16(v);
    lo = __float2bfloat16(v - __bfloat162float(hi));
}

// ============================================================================
// split kernels: fp32 -> (hi, lo) bf16
// ============================================================================
__global__ __launch_bounds__(256) void k_split_x(const float* __restrict__ x) {
    size_t i = ((size_t)blockIdx.x * 256 + threadIdx.x) * 4;
    float4 v = *(const float4*)(x + i);
    __nv_bfloat16 h0, h1, h2, h3, l0, l1, l2, l3;
    split_bf(v.x, h0, l0); split_bf(v.y, h1, l1);
    split_bf(v.z, h2, l2); split_bf(v.w, h3, l3);
    *(__nv_bfloat162*)(g_xhi + i)     = __halves2bfloat162(h0, h1);
    *(__nv_bfloat162*)(g_xhi + i + 2) = __halves2bfloat162(h2, h3);
    *(__nv_bfloat162*)(g_xlo + i)     = __halves2bfloat162(l0, l1);
    *(__nv_bfloat162*)(g_xlo + i + 2) = __halves2bfloat162(l2, l3);
}
__global__ __launch_bounds__(256) void k_split_w(const float* __restrict__ W) {
    size_t i = ((size_t)blockIdx.x * 256 + threadIdx.x) * 4;
    float4 v = *(const float4*)(W + i);
    __nv_bfloat16 h0, h1, h2, h3, l0, l1, l2, l3;
    split_bf(v.x, h0, l0); split_bf(v.y, h1, l1);
    split_bf(v.z, h2, l2); split_bf(v.w, h3, l3);
    *(__nv_bfloat162*)(g_whi + i)     = __halves2bfloat162(h0, h1);
    *(__nv_bfloat162*)(g_whi + i + 2) = __halves2bfloat162(h2, h3);
    *(__nv_bfloat162*)(g_wlo + i)     = __halves2bfloat162(l0, l1);
    *(__nv_bfloat162*)(g_wlo + i + 2) = __halves2bfloat162(l2, l3);
}

// ============================================================================
// K1: qkv = x @ Wqkv via bf16-split mma.  BM=256, BN=128, BK=32, 512 thr.
// q,k cols -> fp32 g_qk; v cols -> bf16 hi/lo g_vhi/g_vlo.
// smem stage (halves): Ah[256*40] Al[256*40] Bh[32*136] Bl[32*136] = 29184
// ============================================================================
__global__ __launch_bounds__(512, 1) void k1_gemm() {
    extern __shared__ __nv_bfloat16 sm[];
    const int tid = threadIdx.x, lane = tid & 31, warp = tid >> 5;
    const int mw = warp >> 2, nw = warp & 3;
    const int row0 = blockIdx.x * 256, col0 = blockIdx.y * 128;

    __nv_bfloat16 *sAh[2], *sAl[2], *sBh[2], *sBl[2];
    #pragma unroll
    for (int s = 0; s < 2; s++) {
        __nv_bfloat16* base = sm + s * 29184;
        sAh[s] = base; sAl[s] = base + 10240;
        sBh[s] = base + 20480; sBl[s] = base + 24832;
    }

    auto load_stage = [&](int s, int kt) {
        const int k0 = kt * 32;
        #pragma unroll
        for (int i = 0; i < 2; i++) {
            int ch = tid * 2 + i; int ar = ch >> 2; int ac = (ch & 3) * 8;
            const size_t go = (size_t)(row0 + ar) * 256 + k0 + ac;
            cp16(sAh[s] + ar * 40 + ac, g_xhi + go);
            cp16(sAl[s] + ar * 40 + ac, g_xlo + go);
        }
        {
            int br = tid >> 4; int bc = (tid & 15) * 8;
            const size_t go = (size_t)(k0 + br) * 768 + col0 + bc;
            cp16(sBh[s] + br * 136 + bc, g_whi + go);
            cp16(sBl[s] + br * 136 + bc, g_wlo + go);
        }
        cp_commit();
    };

    float acc[4][4][4];
    #pragma unroll
    for (int mt = 0; mt < 4; mt++)
        #pragma unroll
        for (int nt = 0; nt < 4; nt++)
            #pragma unroll
            for (int i = 0; i < 4; i++) acc[mt][nt][i] = 0.f;

    load_stage(0, 0);
    for (int kt = 0; kt < 8; kt++) {
        int cur = kt & 1;
        if (kt < 7) { load_stage(1 - cur, kt + 1); cp_wait<1>(); }
        else cp_wait<0>();
        __syncthreads();
        #pragma unroll
        for (int sub = 0; sub < 2; sub++) {
            uint32_t ahi[4][4], alo[4][4], bhi[2][4], blo[2][4];
            #pragma unroll
            for (int mt = 0; mt < 4; mt++) {
                int r = mw * 64 + mt * 16 + (lane & 15);
                int c = sub * 16 + ((lane >> 4) << 3);
                ldsm4(ahi[mt], sAh[cur] + r * 40 + c);
                ldsm4(alo[mt], sAl[cur] + r * 40 + c);
            }
            #pragma unroll
            for (int bt = 0; bt < 2; bt++) {
                int r = sub * 16 + (lane & 15);
                int c = nw * 32 + bt * 16 + ((lane >> 4) << 3);
                ldsm4t(bhi[bt], sBh[cur] + r * 136 + c);
                ldsm4t(blo[bt], sBl[cur] + r * 136 + c);
            }
            #pragma unroll
            for (int mt = 0; mt < 4; mt++)
                #pragma unroll
                for (int nt = 0; nt < 4; nt++) {
                    const uint32_t* bh = &bhi[nt >> 1][(nt & 1) * 2];
                    const uint32_t* bl = &blo[nt >> 1][(nt & 1) * 2];
                    mma16816(acc[mt][nt], ahi[mt], bh);
                    mma16816(acc[mt][nt], ahi[mt], bl);
                    mma16816(acc[mt][nt], alo[mt], bh);
                }
        }
        __syncthreads();
    }

    const bool isV = (col0 >= 512);
    #pragma unroll
    for (int mt = 0; mt < 4; mt++) {
        int r = row0 + mw * 64 + mt * 16 + (lane >> 2);
        #pragma unroll
        for (int nt = 0; nt < 4; nt++) {
            int c = col0 + nw * 32 + nt * 8 + ((lane & 3) << 1);
            float2 p0 = make_float2(acc[mt][nt][0], acc[mt][nt][1]);
            float2 p1 = make_float2(acc[mt][nt][2], acc[mt][nt][3]);
            if (!isV) {
                *(float2*)(g_qk + (size_t)r * 512 + c)       = p0;
                *(float2*)(g_qk + (size_t)(r + 8) * 512 + c) = p1;
            } else {
                int cv = c - 512;
                __nv_bfloat16 h0, h1, l0, l1;
                split_bf(p0.x, h0, l0); split_bf(p0.y, h1, l1);
                *(__nv_bfloat162*)(g_vhi + (size_t)r * 256 + cv) = __halves2bfloat162(h0, h1);
                *(__nv_bfloat162*)(g_vlo + (size_t)r * 256 + cv) = __halves2bfloat162(l0, l1);
                split_bf(p1.x, h0, l0); split_bf(p1.y, h1, l1);
                *(__nv_bfloat162*)(g_vhi + (size_t)(r + 8) * 256 + cv) = __halves2bfloat162(h0, h1);
                *(__nv_bfloat162*)(g_vlo + (size_t)(r + 8) * 256 + cv) = __halves2bfloat162(l0, l1);
            }
        }
    }
}

// ============================================================================
// K2: per (b,h,seg): partial sum exp(k) per d, partial exp(k)^T @ q
// ============================================================================
__global__ __launch_bounds__(256) void k_stats() {
    int bh = blockIdx.x, b = bh >> 3, h = bh & 7, seg = blockIdx.y;
    int tid = threadIdx.x, warp = tid >> 5, lane = tid & 31;

    __shared__ __align__(16) float ksh[8][32];
    __shared__ __align__(16) float qsh[8][32];
    __shared__ float ssum[8][32];

    const float* base = g_qk + (size_t)(b * NSEQ + seg * SEGROWS) * 512;
    int kcol = 256 + h * 32 + lane;
    int qcol = h * 32 + lane;

    int d = tid >> 3, e0 = (tid & 7) * 4;
    float acc[4] = {0.f, 0.f, 0.f, 0.f};
    float mysum = 0.f;

    for (int r0 = 0; r0 < SEGROWS; r0 += 8) {
        const float* rowp = base + (size_t)(r0 + warp) * 512;
        float kv = expf(rowp[kcol]);
        float qv = rowp[qcol];
        mysum += kv;
        __syncthreads();
        ksh[warp][lane] = kv;
        qsh[warp][lane] = qv;
        __syncthreads();
        #pragma unroll
        for (int r = 0; r < 8; r++) {
            float kd = ksh[r][d];
            float4 q4 = *(const float4*)&qsh[r][e0];
            acc[0] += kd * q4.x; acc[1] += kd * q4.y;
            acc[2] += kd * q4.z; acc[3] += kd * q4.w;
        }
    }
    ssum[warp][lane] = mysum;
    __syncthreads();
    if (warp == 0) {
        float s = 0.f;
        #pragma unroll
        for (int w = 0; w < 8; w++) s += ssum[w][lane];
        g_Spart[(bh * SEGS + seg) * 32 + lane] = s;
    }
    float* ap = g_Apart + (size_t)(bh * SEGS + seg) * 1024;
    #pragma unroll
    for (int j = 0; j < 4; j++) ap[d * 32 + e0 + j] = acc[j];
}

// ============================================================================
// K3: combine -> A[bh][d][e] = SCALE * sum(parts)/sumExp_d
// ============================================================================
__global__ __launch_bounds__(256) void k_combine() {
    int bh = blockIdx.x, tid = threadIdx.x;
    __shared__ float sinv[32];
    if (tid < 32) {
        float s = 0.f;
        for (int seg = 0; seg < SEGS; seg++) s += g_Spart[(bh * SEGS + seg) * 32 + tid];
        sinv[tid] = SCALE_ / s;
    }
    __syncthreads();
    for (int idx = tid; idx < 1024; idx += 256) {
        float a = 0.f;
        for (int seg = 0; seg < SEGS; seg++)
            a += g_Apart[(size_t)(bh * SEGS + seg) * 1024 + idx];
        g_A[bh * 1024 + idx] = a * sinv[idx >> 5];
    }
}

// ============================================================================
// K3b: W2[bh][l*32+d][c] = sum_e A[bh][d][e] * Wout[l*32+e][c], split to bf16
// ============================================================================
__global__ __launch_bounds__(256) void k_w2(const float* __restrict__ Wout) {
    __shared__ float A_s[1024];
    __shared__ float Wsh[32 * 256];
    int bh = blockIdx.x, tid = threadIdx.x;
    for (int i = tid; i < 1024; i += 256) A_s[i] = g_A[bh * 1024 + i];
    for (int l = 0; l < 8; l++) {
        __syncthreads();
        const float4* wsrc = (const float4*)(Wout + l * 32 * 256);
        float4* wdst = (float4*)Wsh;
        for (int i = tid; i < 2048; i += 256) wdst[i] = wsrc[i];
        __syncthreads();
        int c = tid;
        for (int d = 0; d < 32; d++) {
            float s = 0.f;
            #pragma unroll
            for (int e = 0; e < 32; e++) s += A_s[d * 32 + e] * Wsh[e * 256 + c];
            __nv_bfloat16 hi, lo; split_bf(s, hi, lo);
            size_t off = (size_t)bh * 65536 + (size_t)(l * 32 + d) * 256 + c;
            g_w2hi[off] = hi; g_w2lo[off] = lo;
        }
    }
}

// ============================================================================
// K4: per (b,h): Y[1024x256] = Vcat @ W2 + bias, LayerNorm, write out.
// BM=64, BN=256, BK=32 (one l per k-tile), 512 thr, bf16-split mma.
// smem stage (halves): Ah[64*40] Al[64*40] Bh[32*264] Bl[32*264] = 22016
// ============================================================================
__global__ __launch_bounds__(512, 1) void k4_out(const float* __restrict__ bout,
                                                 const float* __restrict__ gamma,
                                                 const float* __restrict__ beta,
                                                 float* __restrict__ out) {
    extern __shared__ __nv_bfloat16 sm[];
    const int tid = threadIdx.x, lane = tid & 31, warp = tid >> 5;
    const int mw = warp >> 3, nw = warp & 7;
    const int bh = blockIdx.y, b = bh >> 3, h = bh & 7;
    const int t0 = blockIdx.x * 64;

    __nv_bfloat16 *sAh[2], *sAl[2], *sBh[2], *sBl[2];
    #pragma unroll
    for (int s = 0; s < 2; s++) {
        __nv_bfloat16* base = sm + s * 22016;
        sAh[s] = base; sAl[s] = base + 2560;
        sBh[s] = base + 5120; sBl[s] = base + 13568;
    }

    auto load_stage = [&](int s, int kt) {
        {
            int ch = tid & 255; int ar = ch >> 2; int ac = (ch & 3) * 8;
            const size_t go = ((size_t)(b * 8192) + (size_t)(t0 + ar) * 8 + kt) * 256 + h * 32 + ac;
            if (tid < 256) cp16(sAh[s] + ar * 40 + ac, g_vhi + go);
            else           cp16(sAl[s] + ar * 40 + ac, g_vlo + go);
        }
        #pragma unroll
        for (int i = 0; i < 2; i++) {
            int ch = tid * 2 + i; int br = ch >> 5; int bc = (ch & 31) * 8;
            const size_t go = (size_t)bh * 65536 + (size_t)(kt * 32 + br) * 256 + bc;
            cp16(sBh[s] + br * 264 + bc, g_w2hi + go);
            cp16(sBl[s] + br * 264 + bc, g_w2lo + go);
        }
        cp_commit();
    };

    float acc[2][4][4];
    #pragma unroll
    for (int mt = 0; mt < 2; mt++)
        #pragma unroll
        for (int nt = 0; nt < 4; nt++)
            #pragma unroll
            for (int i = 0; i < 4; i++) acc[mt][nt][i] = 0.f;

    load_stage(0, 0);
    for (int kt = 0; kt < 8; kt++) {
        int cur = kt & 1;
        if (kt < 7) { load_stage(1 - cur, kt + 1); cp_wait<1>(); }
        else cp_wait<0>();
        __syncthreads();
        #pragma unroll
        for (int sub = 0; sub < 2; sub++) {
            uint32_t ahi[2][4], alo[2][4], bhi[2][4], blo[2][4];
            #pragma unroll
            for (int mt = 0; mt < 2; mt++) {
                int r = mw * 32 + mt * 16 + (lane & 15);
                int c = sub * 16 + ((lane >> 4) << 3);
                ldsm4(ahi[mt], sAh[cur] + r * 40 + c);
                ldsm4(alo[mt], sAl[cur] + r * 40 + c);
            }
            #pragma unroll
            for (int bt = 0; bt < 2; bt++) {
                int r = sub * 16 + (lane & 15);
                int c = nw * 32 + bt * 16 + ((lane >> 4) << 3);
                ldsm4t(bhi[bt], sBh[cur] + r * 264 + c);
                ldsm4t(blo[bt], sBl[cur] + r * 264 + c);
            }
            #pragma unroll
            for (int mt = 0; mt < 2; mt++)
                #pragma unroll
                for (int nt = 0; nt < 4; nt++) {
                    const uint32_t* bhp = &bhi[nt >> 1][(nt & 1) * 2];
                    const uint32_t* blp = &blo[nt >> 1][(nt & 1) * 2];
                    mma16816(acc[mt][nt], ahi[mt], bhp);
                    mma16816(acc[mt][nt], ahi[mt], blp);
                    mma16816(acc[mt][nt], alo[mt], bhp);
                }
        }
        __syncthreads();
    }

    // ---------------- epilogue: bias + LayerNorm -----------------------------
    float* red   = (float*)sm;
    float* sred  = red;            // [64][8]
    float* s2red = red + 512;      // [64][8]
    float* mus   = red + 1024;     // [64]
    float* rst   = red + 1088;     // [64]

    float bo[4][2];
    #pragma unroll
    for (int nt = 0; nt < 4; nt++) {
        int c = nw * 32 + nt * 8 + ((lane & 3) << 1);
        float2 bv = *(const float2*)(bout + c);
        bo[nt][0] = bv.x; bo[nt][1] = bv.y;
    }

    #pragma unroll
    for (int mt = 0; mt < 2; mt++)
        #pragma unroll
        for (int half = 0; half < 2; half++) {
            float s = 0.f, s2 = 0.f;
            #pragma unroll
            for (int nt = 0; nt < 4; nt++) {
                float v0 = acc[mt][nt][half * 2 + 0] + bo[nt][0];
                float v1 = acc[mt][nt][half * 2 + 1] + bo[nt][1];
                s += v0 + v1; s2 += v0 * v0 + v1 * v1;
            }
            s  += __shfl_xor_sync(0xffffffffu, s, 1);
            s  += __shfl_xor_sync(0xffffffffu, s, 2);
            s2 += __shfl_xor_sync(0xffffffffu, s2, 1);
            s2 += __shfl_xor_sync(0xffffffffu, s2, 2);
            if ((lane & 3) == 0) {
                int rl = mw * 32 + mt * 16 + (lane >> 2) + half * 8;
                sred[rl * 8 + nw] = s;
                s2red[rl * 8 + nw] = s2;
            }
        }
    __syncthreads();
    if (tid < 64) {
        float s = 0.f, s2 = 0.f;
        #pragma unroll
        for (int w = 0; w < 8; w++) { s += sred[tid * 8 + w]; s2 += s2red[tid * 8 + w]; }
        float mu = s * (1.f / 256.f);
        float var = s2 * (1.f / 256.f) - mu * mu;
        mus[tid] = mu;
        rst[tid] = rsqrtf(var + LN_EPS);
    }
    __syncthreads();

    #pragma unroll
    for (int mt = 0; mt < 2; mt++)
        #pragma unroll
        for (int half = 0; half < 2; half++) {
            int rl = mw * 32 + mt * 16 + (lane >> 2) + half * 8;
            float mu = mus[rl], rs = rst[rl];
            size_t orow = ((size_t)b * 8192 + (size_t)h * 1024 + t0 + rl) * 256;
            #pragma unroll
            for (int nt = 0; nt < 4; nt++) {
                int c = nw * 32 + nt * 8 + ((lane & 3) << 1);
                float2 g = *(const float2*)(gamma + c);
                float2 be = *(const float2*)(beta + c);
                float v0 = acc[mt][nt][half * 2 + 0] + bo[nt][0];
                float v1 = acc[mt][nt][half * 2 + 1] + bo[nt][1];
                float2 o = make_float2((v0 - mu) * rs * g.x + be.x,
                                       (v1 - mu) * rs * g.y + be.y);
                *(float2*)(out + orow + c) = o;
            }
        }
}

// ============================================================================
extern "C" void kernel_launch(void* const* d_in, const int* in_sizes, int n_in,
                              void* d_out, int out_size) {
    const float* x     = (const float*)d_in[0];
    const float* Wqkv  = (const float*)d_in[1];
    const float* Wout  = (const float*)d_in[2];
    const float* bout  = (const float*)d_in[3];
    const float* gamma = (const float*)d_in[4];
    const float* beta  = (const float*)d_in[5];
    float* out = (float*)d_out;

    static bool attr_done = false;
    if (!attr_done) {
        cudaFuncSetAttribute(k1_gemm, cudaFuncAttributeMaxDynamicSharedMemorySize, 2 * 29184 * 2);
        cudaFuncSetAttribute(k4_out,  cudaFuncAttributeMaxDynamicSharedMemorySize, 2 * 22016 * 2);
        attr_done = true;
    }

    k_split_x<<<16384, 256>>>(x);
    k_split_w<<<192, 256>>>(Wqkv);
    k1_gemm<<<dim3(256, 6), 512, 2 * 29184 * 2>>>();
    k_stats<<<dim3(64, 16), 256>>>();
    k_combine<<<64, 256>>>();
    k_w2<<<64, 256>>>(Wout);
    k4_out<<<dim3(16, 64), 512, 2 * 22016 * 2>>>(bout, gamma, beta, out);
}

// round 3
// speedup vs baseline: 2.7769x; 1.0692x over previous
#include <cuda_runtime.h>
#include <cuda_bf16.h>
#include <math.h>
#include <stdint.h>

#define B_      8
#define NSEQ    8192
#define NROWS   65536
#define SCALE_  0.0625f
#define SEGS    16
#define SEGROWS 512
#define LN_EPS  1e-5f

// ---------------- scratch ----------------------------------------------------
__device__ float         g_qk[(size_t)NROWS * 512];          // q (0..255), k (256..511) fp32
__device__ __nv_bfloat16 g_xhi[(size_t)NROWS * 256];
__device__ __nv_bfloat16 g_xlo[(size_t)NROWS * 256];
__device__ __nv_bfloat16 g_whi[256 * 768];
__device__ __nv_bfloat16 g_wlo[256 * 768];
__device__ __nv_bfloat16 g_vhi[(size_t)NROWS * 256];
__device__ __nv_bfloat16 g_vlo[(size_t)NROWS * 256];
__device__ float g_Apart[64 * SEGS * 32 * 32];
__device__ float g_Spart[64 * SEGS * 32];
__device__ float g_A[64 * 32 * 32];
__device__ __nv_bfloat16 g_w2hi[64 * 256 * 256];
__device__ __nv_bfloat16 g_w2lo[64 * 256 * 256];

// ---------------- PTX helpers ------------------------------------------------
__device__ __forceinline__ uint32_t smem_u32(const void* p) {
    return (uint32_t)__cvta_generic_to_shared(p);
}
__device__ __forceinline__ void cp16(void* dst, const void* src) {
    asm volatile("cp.async.cg.shared.global [%0], [%1], 16;\n"
                 :: "r"(smem_u32(dst)), "l"(src));
}
__device__ __forceinline__ void cp_commit() { asm volatile("cp.async.commit_group;\n"); }
template<int N> __device__ __forceinline__ void cp_wait() {
    asm volatile("cp.async.wait_group %0;\n" :: "n"(N));
}
__device__ __forceinline__ void ldsm4(uint32_t (&r)[4], const void* p) {
    asm volatile("ldmatrix.sync.aligned.m8n8.x4.shared.b16 {%0,%1,%2,%3}, [%4];"
                 : "=r"(r[0]), "=r"(r[1]), "=r"(r[2]), "=r"(r[3]) : "r"(smem_u32(p)));
}
__device__ __forceinline__ void ldsm4t(uint32_t (&r)[4], const void* p) {
    asm volatile("ldmatrix.sync.aligned.m8n8.x4.trans.shared.b16 {%0,%1,%2,%3}, [%4];"
                 : "=r"(r[0]), "=r"(r[1]), "=r"(r[2]), "=r"(r[3]) : "r"(smem_u32(p)));
}
__device__ __forceinline__ void mma16816(float (&d)[4], const uint32_t (&a)[4], const uint32_t* b) {
    asm volatile("mma.sync.aligned.m16n8k16.row.col.f32.bf16.bf16.f32 "
                 "{%0,%1,%2,%3}, {%4,%5,%6,%7}, {%8,%9}, {%0,%1,%2,%3};"
                 : "+f"(d[0]), "+f"(d[1]), "+f"(d[2]), "+f"(d[3])
                 : "r"(a[0]), "r"(a[1]), "r"(a[2]), "r"(a[3]), "r"(b[0]), "r"(b[1]));
}
__device__ __forceinline__ void split_bf(float v, __nv_bfloat16& hi, __nv_bfloat16& lo) {
    hi = __float2bfloat16(v);
    lo = __float2bfloat16(v - __bfloat162float(hi));
}

// ============================================================================
// split kernels: fp32 -> (hi, lo) bf16
// ============================================================================
__global__ __launch_bounds__(256) void k_split_x(const float* __restrict__ x) {
    size_t i = ((size_t)blockIdx.x * 256 + threadIdx.x) * 4;
    float4 v = *(const float4*)(x + i);
    __nv_bfloat16 h0, h1, h2, h3, l0, l1, l2, l3;
    split_bf(v.x, h0, l0); split_bf(v.y, h1, l1);
    split_bf(v.z, h2, l2); split_bf(v.w, h3, l3);
    *(__nv_bfloat162*)(g_xhi + i)     = __halves2bfloat162(h0, h1);
    *(__nv_bfloat162*)(g_xhi + i + 2) = __halves2bfloat162(h2, h3);
    *(__nv_bfloat162*)(g_xlo + i)     = __halves2bfloat162(l0, l1);
    *(__nv_bfloat162*)(g_xlo + i + 2) = __halves2bfloat162(l2, l3);
}
__global__ __launch_bounds__(256) void k_split_w(const float* __restrict__ W) {
    size_t i = ((size_t)blockIdx.x * 256 + threadIdx.x) * 4;
    float4 v = *(const float4*)(W + i);
    __nv_bfloat16 h0, h1, h2, h3, l0, l1, l2, l3;
    split_bf(v.x, h0, l0); split_bf(v.y, h1, l1);
    split_bf(v.z, h2, l2); split_bf(v.w, h3, l3);
    *(__nv_bfloat162*)(g_whi + i)     = __halves2bfloat162(h0, h1);
    *(__nv_bfloat162*)(g_whi + i + 2) = __halves2bfloat162(h2, h3);
    *(__nv_bfloat162*)(g_wlo + i)     = __halves2bfloat162(l0, l1);
    *(__nv_bfloat162*)(g_wlo + i + 2) = __halves2bfloat162(l2, l3);
}

// ============================================================================
// K1: qkv = x @ Wqkv via bf16-split mma.  BM=256, BN=128, BK=32, 512 thr.
// 3-stage cp.async pipeline. smem/stage (bf16): 29184.
// ============================================================================
#define K1_STG 29184
__global__ __launch_bounds__(512, 1) void k1_gemm() {
    extern __shared__ __nv_bfloat16 sm[];
    const int tid = threadIdx.x, lane = tid & 31, warp = tid >> 5;
    const int mw = warp >> 2, nw = warp & 3;
    const int row0 = blockIdx.x * 256, col0 = blockIdx.y * 128;

    __nv_bfloat16 *sAh[3], *sAl[3], *sBh[3], *sBl[3];
    #pragma unroll
    for (int s = 0; s < 3; s++) {
        __nv_bfloat16* base = sm + s * K1_STG;
        sAh[s] = base; sAl[s] = base + 10240;
        sBh[s] = base + 20480; sBl[s] = base + 24832;
    }

    auto load_stage = [&](int s, int kt) {
        const int k0 = kt * 32;
        #pragma unroll
        for (int i = 0; i < 2; i++) {
            int ch = tid * 2 + i; int ar = ch >> 2; int ac = (ch & 3) * 8;
            const size_t go = (size_t)(row0 + ar) * 256 + k0 + ac;
            cp16(sAh[s] + ar * 40 + ac, g_xhi + go);
            cp16(sAl[s] + ar * 40 + ac, g_xlo + go);
        }
        {
            int br = tid >> 4; int bc = (tid & 15) * 8;
            const size_t go = (size_t)(k0 + br) * 768 + col0 + bc;
            cp16(sBh[s] + br * 136 + bc, g_whi + go);
            cp16(sBl[s] + br * 136 + bc, g_wlo + go);
        }
        cp_commit();
    };

    float acc[4][4][4];
    #pragma unroll
    for (int mt = 0; mt < 4; mt++)
        #pragma unroll
        for (int nt = 0; nt < 4; nt++)
            #pragma unroll
            for (int i = 0; i < 4; i++) acc[mt][nt][i] = 0.f;

    load_stage(0, 0);
    load_stage(1, 1);
    for (int kt = 0; kt < 8; kt++) {
        int cur = kt % 3;
        if (kt < 6)       { load_stage((kt + 2) % 3, kt + 2); cp_wait<2>(); }
        else if (kt == 6) cp_wait<1>();
        else              cp_wait<0>();
        __syncthreads();
        #pragma unroll
        for (int sub = 0; sub < 2; sub++) {
            uint32_t ahi[4][4], alo[4][4], bhi[2][4], blo[2][4];
            #pragma unroll
            for (int mt = 0; mt < 4; mt++) {
                int r = mw * 64 + mt * 16 + (lane & 15);
                int c = sub * 16 + ((lane >> 4) << 3);
                ldsm4(ahi[mt], sAh[cur] + r * 40 + c);
                ldsm4(alo[mt], sAl[cur] + r * 40 + c);
            }
            #pragma unroll
            for (int bt = 0; bt < 2; bt++) {
                int r = sub * 16 + (lane & 15);
                int c = nw * 32 + bt * 16 + ((lane >> 4) << 3);
                ldsm4t(bhi[bt], sBh[cur] + r * 136 + c);
                ldsm4t(blo[bt], sBl[cur] + r * 136 + c);
            }
            #pragma unroll
            for (int mt = 0; mt < 4; mt++)
                #pragma unroll
                for (int nt = 0; nt < 4; nt++) {
                    const uint32_t* bh = &bhi[nt >> 1][(nt & 1) * 2];
                    const uint32_t* bl = &blo[nt >> 1][(nt & 1) * 2];
                    mma16816(acc[mt][nt], ahi[mt], bh);
                    mma16816(acc[mt][nt], ahi[mt], bl);
                    mma16816(acc[mt][nt], alo[mt], bh);
                }
        }
        __syncthreads();
    }

    const bool isV = (col0 >= 512);
    #pragma unroll
    for (int mt = 0; mt < 4; mt++) {
        int r = row0 + mw * 64 + mt * 16 + (lane >> 2);
        #pragma unroll
        for (int nt = 0; nt < 4; nt++) {
            int c = col0 + nw * 32 + nt * 8 + ((lane & 3) << 1);
            float2 p0 = make_float2(acc[mt][nt][0], acc[mt][nt][1]);
            float2 p1 = make_float2(acc[mt][nt][2], acc[mt][nt][3]);
            if (!isV) {
                *(float2*)(g_qk + (size_t)r * 512 + c)       = p0;
                *(float2*)(g_qk + (size_t)(r + 8) * 512 + c) = p1;
            } else {
                int cv = c - 512;
                __nv_bfloat16 h0, h1, l0, l1;
                split_bf(p0.x, h0, l0); split_bf(p0.y, h1, l1);
                *(__nv_bfloat162*)(g_vhi + (size_t)r * 256 + cv) = __halves2bfloat162(h0, h1);
                *(__nv_bfloat162*)(g_vlo + (size_t)r * 256 + cv) = __halves2bfloat162(l0, l1);
                split_bf(p1.x, h0, l0); split_bf(p1.y, h1, l1);
                *(__nv_bfloat162*)(g_vhi + (size_t)(r + 8) * 256 + cv) = __halves2bfloat162(h0, h1);
                *(__nv_bfloat162*)(g_vlo + (size_t)(r + 8) * 256 + cv) = __halves2bfloat162(l0, l1);
            }
        }
    }
}

// ============================================================================
// K2: warp-shuffle stats. Each warp handles every 8th row independently:
// lane loads q[r,lane], k[r,lane]; shfl-broadcast feeds 4d x 8e register tile.
// No smem / no syncs in the hot loop.
// ============================================================================
__global__ __launch_bounds__(256) void k_stats() {
    int bh = blockIdx.x, b = bh >> 3, h = bh & 7, seg = blockIdx.y;
    int tid = threadIdx.x, warp = tid >> 5, lane = tid & 31;
    __shared__ float sPart[8][1024];
    __shared__ float ssum[8][32];

    const float* base = g_qk + (size_t)(b * NSEQ + seg * SEGROWS) * 512;
    const int qoff = h * 32 + lane, koff = 256 + h * 32 + lane;
    const int dg = lane & 7, eg = lane >> 3;

    float acc[4][8];
    #pragma unroll
    for (int i = 0; i < 4; i++)
        #pragma unroll
        for (int j = 0; j < 8; j++) acc[i][j] = 0.f;
    float mysum = 0.f;

    for (int t = warp; t < SEGROWS; t += 16) {
        const float* r0 = base + (size_t)t * 512;
        const float* r1 = base + (size_t)(t + 8) * 512;
        float k0 = __expf(r0[koff]);
        float q0 = r0[qoff];
        float k1v = __expf(r1[koff]);
        float q1 = r1[qoff];
        mysum += k0 + k1v;
        float ka0[4], ka1[4], qa0[8], qa1[8];
        #pragma unroll
        for (int i = 0; i < 4; i++) {
            ka0[i] = __shfl_sync(0xffffffffu, k0,  dg * 4 + i);
            ka1[i] = __shfl_sync(0xffffffffu, k1v, dg * 4 + i);
        }
        #pragma unroll
        for (int j = 0; j < 8; j++) {
            qa0[j] = __shfl_sync(0xffffffffu, q0, eg * 8 + j);
            qa1[j] = __shfl_sync(0xffffffffu, q1, eg * 8 + j);
        }
        #pragma unroll
        for (int i = 0; i < 4; i++)
            #pragma unroll
            for (int j = 0; j < 8; j++)
                acc[i][j] += ka0[i] * qa0[j] + ka1[i] * qa1[j];
    }

    ssum[warp][lane] = mysum;
    #pragma unroll
    for (int i = 0; i < 4; i++)
        #pragma unroll
        for (int j = 0; j < 8; j++)
            sPart[warp][(dg * 4 + i) * 32 + eg * 8 + j] = acc[i][j];
    __syncthreads();
    if (warp == 0) {
        float s = 0.f;
        #pragma unroll
        for (int w = 0; w < 8; w++) s += ssum[w][lane];
        g_Spart[(bh * SEGS + seg) * 32 + lane] = s;
    }
    float* ap = g_Apart + (size_t)(bh * SEGS + seg) * 1024;
    #pragma unroll
    for (int c = 0; c < 4; c++) {
        int idx = tid * 4 + c;
        float s = 0.f;
        #pragma unroll
        for (int w = 0; w < 8; w++) s += sPart[w][idx];
        ap[idx] = s;
    }
}

// ============================================================================
// K3: combine -> A[bh][d][e] = SCALE * sum(parts)/sumExp_d
// ============================================================================
__global__ __launch_bounds__(256) void k_combine() {
    int bh = blockIdx.x, tid = threadIdx.x;
    __shared__ float sinv[32];
    if (tid < 32) {
        float s = 0.f;
        for (int seg = 0; seg < SEGS; seg++) s += g_Spart[(bh * SEGS + seg) * 32 + tid];
        sinv[tid] = SCALE_ / s;
    }
    __syncthreads();
    for (int idx = tid; idx < 1024; idx += 256) {
        float a = 0.f;
        for (int seg = 0; seg < SEGS; seg++)
            a += g_Apart[(size_t)(bh * SEGS + seg) * 1024 + idx];
        g_A[bh * 1024 + idx] = a * sinv[idx >> 5];
    }
}

// ============================================================================
// K3b: W2[bh][l*32+d][c] = sum_e A[bh][d][e] * Wout[l*32+e][c], split to bf16
// ============================================================================
__global__ __launch_bounds__(256) void k_w2(const float* __restrict__ Wout) {
    __shared__ float A_s[1024];
    __shared__ float Wsh[32 * 256];
    int bh = blockIdx.x, tid = threadIdx.x;
    for (int i = tid; i < 1024; i += 256) A_s[i] = g_A[bh * 1024 + i];
    for (int l = 0; l < 8; l++) {
        __syncthreads();
        const float4* wsrc = (const float4*)(Wout + l * 32 * 256);
        float4* wdst = (float4*)Wsh;
        for (int i = tid; i < 2048; i += 256) wdst[i] = wsrc[i];
        __syncthreads();
        int c = tid;
        for (int d = 0; d < 32; d++) {
            float s = 0.f;
            #pragma unroll
            for (int e = 0; e < 32; e++) s += A_s[d * 32 + e] * Wsh[e * 256 + c];
            __nv_bfloat16 hi, lo; split_bf(s, hi, lo);
            size_t off = (size_t)bh * 65536 + (size_t)(l * 32 + d) * 256 + c;
            g_w2hi[off] = hi; g_w2lo[off] = lo;
        }
    }
}

// ============================================================================
// K4: per (b,h): Y[1024x256] = Vcat @ W2 + bias, LayerNorm, write out.
// BM=64, BN=256, BK=32, 512 thr, 3-stage pipeline. smem/stage (bf16): 22016.
// ============================================================================
#define K4_STG 22016
__global__ __launch_bounds__(512, 1) void k4_out(const float* __restrict__ bout,
                                                 const float* __restrict__ gamma,
                                                 const float* __restrict__ beta,
                                                 float* __restrict__ out) {
    extern __shared__ __nv_bfloat16 sm[];
    const int tid = threadIdx.x, lane = tid & 31, warp = tid >> 5;
    const int mw = warp >> 3, nw = warp & 7;
    const int bh = blockIdx.y, b = bh >> 3, h = bh & 7;
    const int t0 = blockIdx.x * 64;

    __nv_bfloat16 *sAh[3], *sAl[3], *sBh[3], *sBl[3];
    #pragma unroll
    for (int s = 0; s < 3; s++) {
        __nv_bfloat16* base = sm + s * K4_STG;
        sAh[s] = base; sAl[s] = base + 2560;
        sBh[s] = base + 5120; sBl[s] = base + 13568;
    }

    auto load_stage = [&](int s, int kt) {
        {
            int ch = tid & 255; int ar = ch >> 2; int ac = (ch & 3) * 8;
            const size_t go = ((size_t)(b * 8192) + (size_t)(t0 + ar) * 8 + kt) * 256 + h * 32 + ac;
            if (tid < 256) cp16(sAh[s] + ar * 40 + ac, g_vhi + go);
            else           cp16(sAl[s] + ar * 40 + ac, g_vlo + go);
        }
        #pragma unroll
        for (int i = 0; i < 2; i++) {
            int ch = tid * 2 + i; int br = ch >> 5; int bc = (ch & 31) * 8;
            const size_t go = (size_t)bh * 65536 + (size_t)(kt * 32 + br) * 256 + bc;
            cp16(sBh[s] + br * 264 + bc, g_w2hi + go);
            cp16(sBl[s] + br * 264 + bc, g_w2lo + go);
        }
        cp_commit();
    };

    float acc[2][4][4];
    #pragma unroll
    for (int mt = 0; mt < 2; mt++)
        #pragma unroll
        for (int nt = 0; nt < 4; nt++)
            #pragma unroll
            for (int i = 0; i < 4; i++) acc[mt][nt][i] = 0.f;

    load_stage(0, 0);
    load_stage(1, 1);
    for (int kt = 0; kt < 8; kt++) {
        int cur = kt % 3;
        if (kt < 6)       { load_stage((kt + 2) % 3, kt + 2); cp_wait<2>(); }
        else if (kt == 6) cp_wait<1>();
        else              cp_wait<0>();
        __syncthreads();
        #pragma unroll
        for (int sub = 0; sub < 2; sub++) {
            uint32_t ahi[2][4], alo[2][4], bhi[2][4], blo[2][4];
            #pragma unroll
            for (int mt = 0; mt < 2; mt++) {
                int r = mw * 32 + mt * 16 + (lane & 15);
                int c = sub * 16 + ((lane >> 4) << 3);
                ldsm4(ahi[mt], sAh[cur] + r * 40 + c);
                ldsm4(alo[mt], sAl[cur] + r * 40 + c);
            }
            #pragma unroll
            for (int bt = 0; bt < 2; bt++) {
                int r = sub * 16 + (lane & 15);
                int c = nw * 32 + bt * 16 + ((lane >> 4) << 3);
                ldsm4t(bhi[bt], sBh[cur] + r * 264 + c);
                ldsm4t(blo[bt], sBl[cur] + r * 264 + c);
            }
            #pragma unroll
            for (int mt = 0; mt < 2; mt++)
                #pragma unroll
                for (int nt = 0; nt < 4; nt++) {
                    const uint32_t* bhp = &bhi[nt >> 1][(nt & 1) * 2];
                    const uint32_t* blp = &blo[nt >> 1][(nt & 1) * 2];
                    mma16816(acc[mt][nt], ahi[mt], bhp);
                    mma16816(acc[mt][nt], ahi[mt], blp);
                    mma16816(acc[mt][nt], alo[mt], bhp);
                }
        }
        __syncthreads();
    }

    // ---------------- epilogue: bias + LayerNorm -----------------------------
    float* red   = (float*)sm;
    float* sred  = red;            // [64][8]
    float* s2red = red + 512;      // [64][8]
    float* mus   = red + 1024;     // [64]
    float* rst   = red + 1088;     // [64]

    float bo[4][2];
    #pragma unroll
    for (int nt = 0; nt < 4; nt++) {
        int c = nw * 32 + nt * 8 + ((lane & 3) << 1);
        float2 bv = *(const float2*)(bout + c);
        bo[nt][0] = bv.x; bo[nt][1] = bv.y;
    }

    #pragma unroll
    for (int mt = 0; mt < 2; mt++)
        #pragma unroll
        for (int half = 0; half < 2; half++) {
            float s = 0.f, s2 = 0.f;
            #pragma unroll
            for (int nt = 0; nt < 4; nt++) {
                float v0 = acc[mt][nt][half * 2 + 0] + bo[nt][0];
                float v1 = acc[mt][nt][half * 2 + 1] + bo[nt][1];
                s += v0 + v1; s2 += v0 * v0 + v1 * v1;
            }
            s  += __shfl_xor_sync(0xffffffffu, s, 1);
            s  += __shfl_xor_sync(0xffffffffu, s, 2);
            s2 += __shfl_xor_sync(0xffffffffu, s2, 1);
            s2 += __shfl_xor_sync(0xffffffffu, s2, 2);
            if ((lane & 3) == 0) {
                int rl = mw * 32 + mt * 16 + (lane >> 2) + half * 8;
                sred[rl * 8 + nw] = s;
                s2red[rl * 8 + nw] = s2;
            }
        }
    __syncthreads();
    if (tid < 64) {
        float s = 0.f, s2 = 0.f;
        #pragma unroll
        for (int w = 0; w < 8; w++) { s += sred[tid * 8 + w]; s2 += s2red[tid * 8 + w]; }
        float mu = s * (1.f / 256.f);
        float var = s2 * (1.f / 256.f) - mu * mu;
        mus[tid] = mu;
        rst[tid] = rsqrtf(var + LN_EPS);
    }
    __syncthreads();

    #pragma unroll
    for (int mt = 0; mt < 2; mt++)
        #pragma unroll
        for (int half = 0; half < 2; half++) {
            int rl = mw * 32 + mt * 16 + (lane >> 2) + half * 8;
            float mu = mus[rl], rs = rst[rl];
            size_t orow = ((size_t)b * 8192 + (size_t)h * 1024 + t0 + rl) * 256;
            #pragma unroll
            for (int nt = 0; nt < 4; nt++) {
                int c = nw * 32 + nt * 8 + ((lane & 3) << 1);
                float2 g = *(const float2*)(gamma + c);
                float2 be = *(const float2*)(beta + c);
                float v0 = acc[mt][nt][half * 2 + 0] + bo[nt][0];
                float v1 = acc[mt][nt][half * 2 + 1] + bo[nt][1];
                float2 o = make_float2((v0 - mu) * rs * g.x + be.x,
                                       (v1 - mu) * rs * g.y + be.y);
                *(float2*)(out + orow + c) = o;
            }
        }
}

// ============================================================================
extern "C" void kernel_launch(void* const* d_in, const int* in_sizes, int n_in,
                              void* d_out, int out_size) {
    const float* x     = (const float*)d_in[0];
    const float* Wqkv  = (const float*)d_in[1];
    const float* Wout  = (const float*)d_in[2];
    const float* bout  = (const float*)d_in[3];
    const float* gamma = (const float*)d_in[4];
    const float* beta  = (const float*)d_in[5];
    float* out = (float*)d_out;

    cudaFuncSetAttribute(k1_gemm, cudaFuncAttributeMaxDynamicSharedMemorySize, 3 * K1_STG * 2);
    cudaFuncSetAttribute(k4_out,  cudaFuncAttributeMaxDynamicSharedMemorySize, 3 * K4_STG * 2);

    k_split_x<<<16384, 256>>>(x);
    k_split_w<<<192, 256>>>(Wqkv);
    k1_gemm<<<dim3(256, 6), 512, 3 * K1_STG * 2>>>();
    k_stats<<<dim3(64, 16), 256>>>();
    k_combine<<<64, 256>>>();
    k_w2<<<64, 256>>>(Wout);
    k4_out<<<dim3(16, 64), 512, 3 * K4_STG * 2>>>(bout, gamma, beta, out);
}

// round 4
// speedup vs baseline: 2.9488x; 1.0619x over previous
#include <cuda_runtime.h>
#include <cuda_bf16.h>
#include <math.h>
#include <stdint.h>

#define B_      8
#define NSEQ    8192
#define NROWS   65536
#define SCALE_  0.0625f
#define SEGS    16
#define SEGROWS 512
#define LN_EPS  1e-5f

// ---------------- scratch ----------------------------------------------------
__device__ float         g_q [(size_t)64 * NSEQ * 32];       // [bh][n][32] fp32
__device__ float         g_ek[(size_t)64 * NSEQ * 32];       // exp(k), [bh][n][32]
__device__ __nv_bfloat16 g_xhi[(size_t)NROWS * 256];
__device__ __nv_bfloat16 g_xlo[(size_t)NROWS * 256];
__device__ __nv_bfloat16 g_whi[256 * 768];
__device__ __nv_bfloat16 g_wlo[256 * 768];
__device__ __nv_bfloat16 g_vhi[(size_t)NROWS * 256];
__device__ __nv_bfloat16 g_vlo[(size_t)NROWS * 256];
__device__ float g_Apart[64 * SEGS * 32 * 32];
__device__ float g_Spart[64 * SEGS * 32];
__device__ float g_A[64 * 32 * 32];
__device__ __nv_bfloat16 g_w2hi[64 * 256 * 256];
__device__ __nv_bfloat16 g_w2lo[64 * 256 * 256];

// ---------------- PTX helpers ------------------------------------------------
__device__ __forceinline__ uint32_t smem_u32(const void* p) {
    return (uint32_t)__cvta_generic_to_shared(p);
}
__device__ __forceinline__ void cp16(void* dst, const void* src) {
    asm volatile("cp.async.cg.shared.global [%0], [%1], 16;\n"
                 :: "r"(smem_u32(dst)), "l"(src));
}
__device__ __forceinline__ void cp_commit() { asm volatile("cp.async.commit_group;\n"); }
template<int N> __device__ __forceinline__ void cp_wait() {
    asm volatile("cp.async.wait_group %0;\n" :: "n"(N));
}
__device__ __forceinline__ void ldsm4(uint32_t (&r)[4], const void* p) {
    asm volatile("ldmatrix.sync.aligned.m8n8.x4.shared.b16 {%0,%1,%2,%3}, [%4];"
                 : "=r"(r[0]), "=r"(r[1]), "=r"(r[2]), "=r"(r[3]) : "r"(smem_u32(p)));
}
__device__ __forceinline__ void ldsm4t(uint32_t (&r)[4], const void* p) {
    asm volatile("ldmatrix.sync.aligned.m8n8.x4.trans.shared.b16 {%0,%1,%2,%3}, [%4];"
                 : "=r"(r[0]), "=r"(r[1]), "=r"(r[2]), "=r"(r[3]) : "r"(smem_u32(p)));
}
__device__ __forceinline__ void mma16816(float (&d)[4], const uint32_t (&a)[4], const uint32_t* b) {
    asm volatile("mma.sync.aligned.m16n8k16.row.col.f32.bf16.bf16.f32 "
                 "{%0,%1,%2,%3}, {%4,%5,%6,%7}, {%8,%9}, {%0,%1,%2,%3};"
                 : "+f"(d[0]), "+f"(d[1]), "+f"(d[2]), "+f"(d[3])
                 : "r"(a[0]), "r"(a[1]), "r"(a[2]), "r"(a[3]), "r"(b[0]), "r"(b[1]));
}
__device__ __forceinline__ void split_bf(float v, __nv_bfloat16& hi, __nv_bfloat16& lo) {
    hi = __float2bfloat16(v);
    lo = __float2bfloat16(v - __bfloat162float(hi));
}

// ============================================================================
// split kernels: fp32 -> (hi, lo) bf16
// ============================================================================
__global__ __launch_bounds__(256) void k_split_x(const float* __restrict__ x) {
    size_t i = ((size_t)blockIdx.x * 256 + threadIdx.x) * 4;
    float4 v = *(const float4*)(x + i);
    __nv_bfloat16 h0, h1, h2, h3, l0, l1, l2, l3;
    split_bf(v.x, h0, l0); split_bf(v.y, h1, l1);
    split_bf(v.z, h2, l2); split_bf(v.w, h3, l3);
    *(__nv_bfloat162*)(g_xhi + i)     = __halves2bfloat162(h0, h1);
    *(__nv_bfloat162*)(g_xhi + i + 2) = __halves2bfloat162(h2, h3);
    *(__nv_bfloat162*)(g_xlo + i)     = __halves2bfloat162(l0, l1);
    *(__nv_bfloat162*)(g_xlo + i + 2) = __halves2bfloat162(l2, l3);
}
__global__ __launch_bounds__(256) void k_split_w(const float* __restrict__ W) {
    size_t i = ((size_t)blockIdx.x * 256 + threadIdx.x) * 4;
    float4 v = *(const float4*)(W + i);
    __nv_bfloat16 h0, h1, h2, h3, l0, l1, l2, l3;
    split_bf(v.x, h0, l0); split_bf(v.y, h1, l1);
    split_bf(v.z, h2, l2); split_bf(v.w, h3, l3);
    *(__nv_bfloat162*)(g_whi + i)     = __halves2bfloat162(h0, h1);
    *(__nv_bfloat162*)(g_whi + i + 2) = __halves2bfloat162(h2, h3);
    *(__nv_bfloat162*)(g_wlo + i)     = __halves2bfloat162(l0, l1);
    *(__nv_bfloat162*)(g_wlo + i + 2) = __halves2bfloat162(l2, l3);
}

// ============================================================================
// K1: qkv = x @ Wqkv via bf16-split mma.  BM=256, BN=128, BK=32, 512 thr.
// 3-stage cp.async pipeline. Epilogue routes:
//   q cols  -> g_q  [bh][n][32] fp32
//   k cols  -> g_ek [bh][n][32] fp32 (exp applied here)
//   v cols  -> g_vhi/g_vlo bf16 split
// ============================================================================
#define K1_STG 29184
__global__ __launch_bounds__(512, 1) void k1_gemm() {
    extern __shared__ __nv_bfloat16 sm[];
    const int tid = threadIdx.x, lane = tid & 31, warp = tid >> 5;
    const int mw = warp >> 2, nw = warp & 3;
    const int row0 = blockIdx.x * 256, col0 = blockIdx.y * 128;

    __nv_bfloat16 *sAh[3], *sAl[3], *sBh[3], *sBl[3];
    #pragma unroll
    for (int s = 0; s < 3; s++) {
        __nv_bfloat16* base = sm + s * K1_STG;
        sAh[s] = base; sAl[s] = base + 10240;
        sBh[s] = base + 20480; sBl[s] = base + 24832;
    }

    auto load_stage = [&](int s, int kt) {
        const int k0 = kt * 32;
        #pragma unroll
        for (int i = 0; i < 2; i++) {
            int ch = tid * 2 + i; int ar = ch >> 2; int ac = (ch & 3) * 8;
            const size_t go = (size_t)(row0 + ar) * 256 + k0 + ac;
            cp16(sAh[s] + ar * 40 + ac, g_xhi + go);
            cp16(sAl[s] + ar * 40 + ac, g_xlo + go);
        }
        {
            int br = tid >> 4; int bc = (tid & 15) * 8;
            const size_t go = (size_t)(k0 + br) * 768 + col0 + bc;
            cp16(sBh[s] + br * 136 + bc, g_whi + go);
            cp16(sBl[s] + br * 136 + bc, g_wlo + go);
        }
        cp_commit();
    };

    float acc[4][4][4];
    #pragma unroll
    for (int mt = 0; mt < 4; mt++)
        #pragma unroll
        for (int nt = 0; nt < 4; nt++)
            #pragma unroll
            for (int i = 0; i < 4; i++) acc[mt][nt][i] = 0.f;

    load_stage(0, 0);
    load_stage(1, 1);
    for (int kt = 0; kt < 8; kt++) {
        int cur = kt % 3;
        if (kt < 6)       { load_stage((kt + 2) % 3, kt + 2); cp_wait<2>(); }
        else if (kt == 6) cp_wait<1>();
        else              cp_wait<0>();
        __syncthreads();
        #pragma unroll
        for (int sub = 0; sub < 2; sub++) {
            uint32_t ahi[4][4], alo[4][4], bhi[2][4], blo[2][4];
            #pragma unroll
            for (int mt = 0; mt < 4; mt++) {
                int r = mw * 64 + mt * 16 + (lane & 15);
                int c = sub * 16 + ((lane >> 4) << 3);
                ldsm4(ahi[mt], sAh[cur] + r * 40 + c);
                ldsm4(alo[mt], sAl[cur] + r * 40 + c);
            }
            #pragma unroll
            for (int bt = 0; bt < 2; bt++) {
                int r = sub * 16 + (lane & 15);
                int c = nw * 32 + bt * 16 + ((lane >> 4) << 3);
                ldsm4t(bhi[bt], sBh[cur] + r * 136 + c);
                ldsm4t(blo[bt], sBl[cur] + r * 136 + c);
            }
            #pragma unroll
            for (int mt = 0; mt < 4; mt++)
                #pragma unroll
                for (int nt = 0; nt < 4; nt++) {
                    const uint32_t* bh = &bhi[nt >> 1][(nt & 1) * 2];
                    const uint32_t* bl = &blo[nt >> 1][(nt & 1) * 2];
                    mma16816(acc[mt][nt], ahi[mt], bh);
                    mma16816(acc[mt][nt], ahi[mt], bl);
                    mma16816(acc[mt][nt], alo[mt], bh);
                }
        }
        __syncthreads();
    }

    #pragma unroll
    for (int mt = 0; mt < 4; mt++) {
        int r = row0 + mw * 64 + mt * 16 + (lane >> 2);
        int b = r >> 13, n = r & 8191;
        #pragma unroll
        for (int nt = 0; nt < 4; nt++) {
            int c = col0 + nw * 32 + nt * 8 + ((lane & 3) << 1);
            float2 p0 = make_float2(acc[mt][nt][0], acc[mt][nt][1]);
            float2 p1 = make_float2(acc[mt][nt][2], acc[mt][nt][3]);
            if (c < 256) {                      // q -> [bh][n][32]
                int h = c >> 5, cl = c & 31;
                float* dst = g_q + ((size_t)(b * 8 + h) * NSEQ + n) * 32 + cl;
                *(float2*)dst = p0;
                *(float2*)(dst + 8 * 32) = p1;
            } else if (c < 512) {               // exp(k) -> [bh][n][32]
                int ck = c - 256;
                int h = ck >> 5, cl = ck & 31;
                float* dst = g_ek + ((size_t)(b * 8 + h) * NSEQ + n) * 32 + cl;
                *(float2*)dst = make_float2(__expf(p0.x), __expf(p0.y));
                *(float2*)(dst + 8 * 32) = make_float2(__expf(p1.x), __expf(p1.y));
            } else {                            // v -> bf16 split
                int cv = c - 512;
                __nv_bfloat16 h0, h1, l0, l1;
                split_bf(p0.x, h0, l0); split_bf(p0.y, h1, l1);
                *(__nv_bfloat162*)(g_vhi + (size_t)r * 256 + cv) = __halves2bfloat162(h0, h1);
                *(__nv_bfloat162*)(g_vlo + (size_t)r * 256 + cv) = __halves2bfloat162(l0, l1);
                split_bf(p1.x, h0, l0); split_bf(p1.y, h1, l1);
                *(__nv_bfloat162*)(g_vhi + (size_t)(r + 8) * 256 + cv) = __halves2bfloat162(h0, h1);
                *(__nv_bfloat162*)(g_vlo + (size_t)(r + 8) * 256 + cv) = __halves2bfloat162(l0, l1);
            }
        }
    }
}

// ============================================================================
// K2: stats on contiguous [bh][n][32] streams. Warp w: rows w*64..w*64+63.
// Per row: lane loads q,ek; shfl broadcast feeds 4d x 8e register tile.
// ============================================================================
__global__ __launch_bounds__(256) void k_stats() {
    int bh = blockIdx.x, seg = blockIdx.y;
    int tid = threadIdx.x, warp = tid >> 5, lane = tid & 31;
    __shared__ float sPart[8][1024];
    __shared__ float ssum[8][32];

    const float* qb = g_q  + ((size_t)bh * NSEQ + seg * SEGROWS) * 32;
    const float* eb = g_ek + ((size_t)bh * NSEQ + seg * SEGROWS) * 32;
    const int dg = lane & 7, eg = lane >> 3;

    float acc[4][8];
    #pragma unroll
    for (int i = 0; i < 4; i++)
        #pragma unroll
        for (int j = 0; j < 8; j++) acc[i][j] = 0.f;
    float mysum = 0.f;

    const int t0 = warp * 64;
    for (int t = t0; t < t0 + 64; t += 4) {
        float ev[4], qv[4];
        #pragma unroll
        for (int u = 0; u < 4; u++) {
            ev[u] = eb[(size_t)(t + u) * 32 + lane];
            qv[u] = qb[(size_t)(t + u) * 32 + lane];
        }
        #pragma unroll
        for (int u = 0; u < 4; u++) {
            mysum += ev[u];
            float ka[4], qa[8];
            #pragma unroll
            for (int i = 0; i < 4; i++) ka[i] = __shfl_sync(0xffffffffu, ev[u], dg * 4 + i);
            #pragma unroll
            for (int j = 0; j < 8; j++) qa[j] = __shfl_sync(0xffffffffu, qv[u], eg * 8 + j);
            #pragma unroll
            for (int i = 0; i < 4; i++)
                #pragma unroll
                for (int j = 0; j < 8; j++) acc[i][j] += ka[i] * qa[j];
        }
    }

    ssum[warp][lane] = mysum;
    #pragma unroll
    for (int i = 0; i < 4; i++)
        #pragma unroll
        for (int j = 0; j < 8; j++)
            sPart[warp][(dg * 4 + i) * 32 + eg * 8 + j] = acc[i][j];
    __syncthreads();
    if (warp == 0) {
        float s = 0.f;
        #pragma unroll
        for (int w = 0; w < 8; w++) s += ssum[w][lane];
        g_Spart[(bh * SEGS + seg) * 32 + lane] = s;
    }
    float* ap = g_Apart + (size_t)(bh * SEGS + seg) * 1024;
    #pragma unroll
    for (int c = 0; c < 4; c++) {
        int idx = tid * 4 + c;
        float s = 0.f;
        #pragma unroll
        for (int w = 0; w < 8; w++) s += sPart[w][idx];
        ap[idx] = s;
    }
}

// ============================================================================
// K3: combine -> A[bh][d][e] = SCALE * sum(parts)/sumExp_d
// ============================================================================
__global__ __launch_bounds__(256) void k_combine() {
    int bh = blockIdx.x, tid = threadIdx.x;
    __shared__ float sinv[32];
    if (tid < 32) {
        float s = 0.f;
        for (int seg = 0; seg < SEGS; seg++) s += g_Spart[(bh * SEGS + seg) * 32 + tid];
        sinv[tid] = SCALE_ / s;
    }
    __syncthreads();
    for (int idx = tid; idx < 1024; idx += 256) {
        float a = 0.f;
        for (int seg = 0; seg < SEGS; seg++)
            a += g_Apart[(size_t)(bh * SEGS + seg) * 1024 + idx];
        g_A[bh * 1024 + idx] = a * sinv[idx >> 5];
    }
}

// ============================================================================
// K3b: W2[bh][l*32+d][c] = sum_e A[bh][d][e] * Wout[l*32+e][c], split to bf16
// ============================================================================
__global__ __launch_bounds__(256) void k_w2(const float* __restrict__ Wout) {
    __shared__ float A_s[1024];
    __shared__ float Wsh[32 * 256];
    int bh = blockIdx.x, tid = threadIdx.x;
    for (int i = tid; i < 1024; i += 256) A_s[i] = g_A[bh * 1024 + i];
    for (int l = 0; l < 8; l++) {
        __syncthreads();
        const float4* wsrc = (const float4*)(Wout + l * 32 * 256);
        float4* wdst = (float4*)Wsh;
        for (int i = tid; i < 2048; i += 256) wdst[i] = wsrc[i];
        __syncthreads();
        int c = tid;
        for (int d = 0; d < 32; d++) {
            float s = 0.f;
            #pragma unroll
            for (int e = 0; e < 32; e++) s += A_s[d * 32 + e] * Wsh[e * 256 + c];
            __nv_bfloat16 hi, lo; split_bf(s, hi, lo);
            size_t off = (size_t)bh * 65536 + (size_t)(l * 32 + d) * 256 + c;
            g_w2hi[off] = hi; g_w2lo[off] = lo;
        }
    }
}

// ============================================================================
// K4: per (b,h): Y[1024x256] = Vcat @ W2 + bias, LayerNorm, write out.
// BM=64, BN=256, BK=32, 512 thr, 3-stage pipeline.
// ============================================================================
#define K4_STG 22016
__global__ __launch_bounds__(512, 1) void k4_out(const float* __restrict__ bout,
                                                 const float* __restrict__ gamma,
                                                 const float* __restrict__ beta,
                                                 float* __restrict__ out) {
    extern __shared__ __nv_bfloat16 sm[];
    const int tid = threadIdx.x, lane = tid & 31, warp = tid >> 5;
    const int mw = warp >> 3, nw = warp & 7;
    const int bh = blockIdx.y, b = bh >> 3, h = bh & 7;
    const int t0 = blockIdx.x * 64;

    __nv_bfloat16 *sAh[3], *sAl[3], *sBh[3], *sBl[3];
    #pragma unroll
    for (int s = 0; s < 3; s++) {
        __nv_bfloat16* base = sm + s * K4_STG;
        sAh[s] = base; sAl[s] = base + 2560;
        sBh[s] = base + 5120; sBl[s] = base + 13568;
    }

    auto load_stage = [&](int s, int kt) {
        {
            int ch = tid & 255; int ar = ch >> 2; int ac = (ch & 3) * 8;
            const size_t go = ((size_t)(b * 8192) + (size_t)(t0 + ar) * 8 + kt) * 256 + h * 32 + ac;
            if (tid < 256) cp16(sAh[s] + ar * 40 + ac, g_vhi + go);
            else           cp16(sAl[s] + ar * 40 + ac, g_vlo + go);
        }
        #pragma unroll
        for (int i = 0; i < 2; i++) {
            int ch = tid * 2 + i; int br = ch >> 5; int bc = (ch & 31) * 8;
            const size_t go = (size_t)bh * 65536 + (size_t)(kt * 32 + br) * 256 + bc;
            cp16(sBh[s] + br * 264 + bc, g_w2hi + go);
            cp16(sBl[s] + br * 264 + bc, g_w2lo + go);
        }
        cp_commit();
    };

    float acc[2][4][4];
    #pragma unroll
    for (int mt = 0; mt < 2; mt++)
        #pragma unroll
        for (int nt = 0; nt < 4; nt++)
            #pragma unroll
            for (int i = 0; i < 4; i++) acc[mt][nt][i] = 0.f;

    load_stage(0, 0);
    load_stage(1, 1);
    for (int kt = 0; kt < 8; kt++) {
        int cur = kt % 3;
        if (kt < 6)       { load_stage((kt + 2) % 3, kt + 2); cp_wait<2>(); }
        else if (kt == 6) cp_wait<1>();
        else              cp_wait<0>();
        __syncthreads();
        #pragma unroll
        for (int sub = 0; sub < 2; sub++) {
            uint32_t ahi[2][4], alo[2][4], bhi[2][4], blo[2][4];
            #pragma unroll
            for (int mt = 0; mt < 2; mt++) {
                int r = mw * 32 + mt * 16 + (lane & 15);
                int c = sub * 16 + ((lane >> 4) << 3);
                ldsm4(ahi[mt], sAh[cur] + r * 40 + c);
                ldsm4(alo[mt], sAl[cur] + r * 40 + c);
            }
            #pragma unroll
            for (int bt = 0; bt < 2; bt++) {
                int r = sub * 16 + (lane & 15);
                int c = nw * 32 + bt * 16 + ((lane >> 4) << 3);
                ldsm4t(bhi[bt], sBh[cur] + r * 264 + c);
                ldsm4t(blo[bt], sBl[cur] + r * 264 + c);
            }
            #pragma unroll
            for (int mt = 0; mt < 2; mt++)
                #pragma unroll
                for (int nt = 0; nt < 4; nt++) {
                    const uint32_t* bhp = &bhi[nt >> 1][(nt & 1) * 2];
                    const uint32_t* blp = &blo[nt >> 1][(nt & 1) * 2];
                    mma16816(acc[mt][nt], ahi[mt], bhp);
                    mma16816(acc[mt][nt], ahi[mt], blp);
                    mma16816(acc[mt][nt], alo[mt], bhp);
                }
        }
        __syncthreads();
    }

    // ---------------- epilogue: bias + LayerNorm -----------------------------
    float* red   = (float*)sm;
    float* sred  = red;            // [64][8]
    float* s2red = red + 512;      // [64][8]
    float* mus   = red + 1024;     // [64]
    float* rst   = red + 1088;     // [64]

    float bo[4][2];
    #pragma unroll
    for (int nt = 0; nt < 4; nt++) {
        int c = nw * 32 + nt * 8 + ((lane & 3) << 1);
        float2 bv = *(const float2*)(bout + c);
        bo[nt][0] = bv.x; bo[nt][1] = bv.y;
    }

    #pragma unroll
    for (int mt = 0; mt < 2; mt++)
        #pragma unroll
        for (int half = 0; half < 2; half++) {
            float s = 0.f, s2 = 0.f;
            #pragma unroll
            for (int nt = 0; nt < 4; nt++) {
                float v0 = acc[mt][nt][half * 2 + 0] + bo[nt][0];
                float v1 = acc[mt][nt][half * 2 + 1] + bo[nt][1];
                s += v0 + v1; s2 += v0 * v0 + v1 * v1;
            }
            s  += __shfl_xor_sync(0xffffffffu, s, 1);
            s  += __shfl_xor_sync(0xffffffffu, s, 2);
            s2 += __shfl_xor_sync(0xffffffffu, s2, 1);
            s2 += __shfl_xor_sync(0xffffffffu, s2, 2);
            if ((lane & 3) == 0) {
                int rl = mw * 32 + mt * 16 + (lane >> 2) + half * 8;
                sred[rl * 8 + nw] = s;
                s2red[rl * 8 + nw] = s2;
            }
        }
    __syncthreads();
    if (tid < 64) {
        float s = 0.f, s2 = 0.f;
        #pragma unroll
        for (int w = 0; w < 8; w++) { s += sred[tid * 8 + w]; s2 += s2red[tid * 8 + w]; }
        float mu = s * (1.f / 256.f);
        float var = s2 * (1.f / 256.f) - mu * mu;
        mus[tid] = mu;
        rst[tid] = rsqrtf(var + LN_EPS);
    }
    __syncthreads();

    #pragma unroll
    for (int mt = 0; mt < 2; mt++)
        #pragma unroll
        for (int half = 0; half < 2; half++) {
            int rl = mw * 32 + mt * 16 + (lane >> 2) + half * 8;
            float mu = mus[rl], rs = rst[rl];
            size_t orow = ((size_t)b * 8192 + (size_t)h * 1024 + t0 + rl) * 256;
            #pragma unroll
            for (int nt = 0; nt < 4; nt++) {
                int c = nw * 32 + nt * 8 + ((lane & 3) << 1);
                float2 g = *(const float2*)(gamma + c);
                float2 be = *(const float2*)(beta + c);
                float v0 = acc[mt][nt][half * 2 + 0] + bo[nt][0];
                float v1 = acc[mt][nt][half * 2 + 1] + bo[nt][1];
                float2 o = make_float2((v0 - mu) * rs * g.x + be.x,
                                       (v1 - mu) * rs * g.y + be.y);
                *(float2*)(out + orow + c) = o;
            }
        }
}

// ============================================================================
extern "C" void kernel_launch(void* const* d_in, const int* in_sizes, int n_in,
                              void* d_out, int out_size) {
    const float* x     = (const float*)d_in[0];
    const float* Wqkv  = (const float*)d_in[1];
    const float* Wout  = (const float*)d_in[2];
    const float* bout  = (const float*)d_in[3];
    const float* gamma = (const float*)d_in[4];
    const float* beta  = (const float*)d_in[5];
    float* out = (float*)d_out;

    cudaFuncSetAttribute(k1_gemm, cudaFuncAttributeMaxDynamicSharedMemorySize, 3 * K1_STG * 2);
    cudaFuncSetAttribute(k4_out,  cudaFuncAttributeMaxDynamicSharedMemorySize, 3 * K4_STG * 2);

    k_split_x<<<16384, 256>>>(x);
    k_split_w<<<192, 256>>>(Wqkv);
    k1_gemm<<<dim3(256, 6), 512, 3 * K1_STG * 2>>>();
    k_stats<<<dim3(64, 16), 256>>>();
    k_combine<<<64, 256>>>();
    k_w2<<<64, 256>>>(Wout);
    k4_out<<<dim3(16, 64), 512, 3 * K4_STG * 2>>>(bout, gamma, beta, out);
}

// round 5
// speedup vs baseline: 3.0075x; 1.0199x over previous
#include <cuda_runtime.h>
#include <cuda_bf16.h>
#include <math.h>
#include <stdint.h>

#define B_      8
#define NSEQ    8192
#define NROWS   65536
#define SCALE_  0.0625f
#define LN_EPS  1e-5f
#define NSEG    8
#define SSEG    1024

// ---------------- scratch ----------------------------------------------------
__device__ __nv_bfloat16 g_qhi[(size_t)64 * NSEQ * 32];
__device__ __nv_bfloat16 g_qlo[(size_t)64 * NSEQ * 32];
__device__ __nv_bfloat16 g_ehi[(size_t)64 * NSEQ * 32];
__device__ __nv_bfloat16 g_elo[(size_t)64 * NSEQ * 32];
__device__ __nv_bfloat16 g_xhi[(size_t)NROWS * 256];
__device__ __nv_bfloat16 g_xlo[(size_t)NROWS * 256];
__device__ __nv_bfloat16 g_whi[256 * 768];
__device__ __nv_bfloat16 g_wlo[256 * 768];
__device__ __nv_bfloat16 g_vhi[(size_t)NROWS * 256];
__device__ __nv_bfloat16 g_vlo[(size_t)NROWS * 256];
__device__ float g_Apart[64 * NSEG * 1024];
__device__ float g_Sp2[256 * 256];            // [rowblk][ek col - 256]
__device__ float g_A[64 * 1024];
__device__ __nv_bfloat16 g_w2hi[64 * 256 * 256];
__device__ __nv_bfloat16 g_w2lo[64 * 256 * 256];

// ---------------- PTX helpers ------------------------------------------------
__device__ __forceinline__ uint32_t smem_u32(const void* p) {
    return (uint32_t)__cvta_generic_to_shared(p);
}
__device__ __forceinline__ void cp16(void* dst, const void* src) {
    asm volatile("cp.async.cg.shared.global [%0], [%1], 16;\n"
                 :: "r"(smem_u32(dst)), "l"(src));
}
__device__ __forceinline__ void cp_commit() { asm volatile("cp.async.commit_group;\n"); }
template<int N> __device__ __forceinline__ void cp_wait() {
    asm volatile("cp.async.wait_group %0;\n" :: "n"(N));
}
__device__ __forceinline__ void ldsm4(uint32_t (&r)[4], const void* p) {
    asm volatile("ldmatrix.sync.aligned.m8n8.x4.shared.b16 {%0,%1,%2,%3}, [%4];"
                 : "=r"(r[0]), "=r"(r[1]), "=r"(r[2]), "=r"(r[3]) : "r"(smem_u32(p)));
}
__device__ __forceinline__ void ldsm4t(uint32_t (&r)[4], const void* p) {
    asm volatile("ldmatrix.sync.aligned.m8n8.x4.trans.shared.b16 {%0,%1,%2,%3}, [%4];"
                 : "=r"(r[0]), "=r"(r[1]), "=r"(r[2]), "=r"(r[3]) : "r"(smem_u32(p)));
}
__device__ __forceinline__ void mma16816(float (&d)[4], const uint32_t (&a)[4], const uint32_t* b) {
    asm volatile("mma.sync.aligned.m16n8k16.row.col.f32.bf16.bf16.f32 "
                 "{%0,%1,%2,%3}, {%4,%5,%6,%7}, {%8,%9}, {%0,%1,%2,%3};"
                 : "+f"(d[0]), "+f"(d[1]), "+f"(d[2]), "+f"(d[3])
                 : "r"(a[0]), "r"(a[1]), "r"(a[2]), "r"(a[3]), "r"(b[0]), "r"(b[1]));
}
__device__ __forceinline__ void split_bf(float v, __nv_bfloat16& hi, __nv_bfloat16& lo) {
    hi = __float2bfloat16(v);
    lo = __float2bfloat16(v - __bfloat162float(hi));
}

// ============================================================================
// split kernels: fp32 -> (hi, lo) bf16
// ============================================================================
__global__ __launch_bounds__(256) void k_split_x(const float* __restrict__ x) {
    size_t i = ((size_t)blockIdx.x * 256 + threadIdx.x) * 4;
    float4 v = *(const float4*)(x + i);
    __nv_bfloat16 h0, h1, h2, h3, l0, l1, l2, l3;
    split_bf(v.x, h0, l0); split_bf(v.y, h1, l1);
    split_bf(v.z, h2, l2); split_bf(v.w, h3, l3);
    *(__nv_bfloat162*)(g_xhi + i)     = __halves2bfloat162(h0, h1);
    *(__nv_bfloat162*)(g_xhi + i + 2) = __halves2bfloat162(h2, h3);
    *(__nv_bfloat162*)(g_xlo + i)     = __halves2bfloat162(l0, l1);
    *(__nv_bfloat162*)(g_xlo + i + 2) = __halves2bfloat162(l2, l3);
}
__global__ __launch_bounds__(256) void k_split_w(const float* __restrict__ W) {
    size_t i = ((size_t)blockIdx.x * 256 + threadIdx.x) * 4;
    float4 v = *(const float4*)(W + i);
    __nv_bfloat16 h0, h1, h2, h3, l0, l1, l2, l3;
    split_bf(v.x, h0, l0); split_bf(v.y, h1, l1);
    split_bf(v.z, h2, l2); split_bf(v.w, h3, l3);
    *(__nv_bfloat162*)(g_whi + i)     = __halves2bfloat162(h0, h1);
    *(__nv_bfloat162*)(g_whi + i + 2) = __halves2bfloat162(h2, h3);
    *(__nv_bfloat162*)(g_wlo + i)     = __halves2bfloat162(l0, l1);
    *(__nv_bfloat162*)(g_wlo + i + 2) = __halves2bfloat162(l2, l3);
}

// ============================================================================
// K1: qkv = x @ Wqkv via bf16-split mma.  BM=256, BN=128, BK=32, 512 thr.
// grid (6 colblks [fastest], 256 rowblks) for L2 reuse of x tiles.
// Epilogue: q -> bf16 split [bh][n][32]; k -> exp, sums, bf16 split; v -> split.
// ============================================================================
#define K1_STG 29184
__global__ __launch_bounds__(512, 1) void k1_gemm() {
    extern __shared__ __nv_bfloat16 sm[];
    const int tid = threadIdx.x, lane = tid & 31, warp = tid >> 5;
    const int mw = warp >> 2, nw = warp & 3;
    const int row0 = blockIdx.y * 256, col0 = blockIdx.x * 128;

    __nv_bfloat16 *sAh[3], *sAl[3], *sBh[3], *sBl[3];
    #pragma unroll
    for (int s = 0; s < 3; s++) {
        __nv_bfloat16* base = sm + s * K1_STG;
        sAh[s] = base; sAl[s] = base + 10240;
        sBh[s] = base + 20480; sBl[s] = base + 24832;
    }

    auto load_stage = [&](int s, int kt) {
        const int k0 = kt * 32;
        #pragma unroll
        for (int i = 0; i < 2; i++) {
            int ch = tid * 2 + i; int ar = ch >> 2; int ac = (ch & 3) * 8;
            const size_t go = (size_t)(row0 + ar) * 256 + k0 + ac;
            cp16(sAh[s] + ar * 40 + ac, g_xhi + go);
            cp16(sAl[s] + ar * 40 + ac, g_xlo + go);
        }
        {
            int br = tid >> 4; int bc = (tid & 15) * 8;
            const size_t go = (size_t)(k0 + br) * 768 + col0 + bc;
            cp16(sBh[s] + br * 136 + bc, g_whi + go);
            cp16(sBl[s] + br * 136 + bc, g_wlo + go);
        }
        cp_commit();
    };

    float acc[4][4][4];
    #pragma unroll
    for (int mt = 0; mt < 4; mt++)
        #pragma unroll
        for (int nt = 0; nt < 4; nt++)
            #pragma unroll
            for (int i = 0; i < 4; i++) acc[mt][nt][i] = 0.f;

    load_stage(0, 0);
    load_stage(1, 1);
    for (int kt = 0; kt < 8; kt++) {
        int cur = kt % 3;
        if (kt < 6)       { load_stage((kt + 2) % 3, kt + 2); cp_wait<2>(); }
        else if (kt == 6) cp_wait<1>();
        else              cp_wait<0>();
        __syncthreads();
        #pragma unroll
        for (int sub = 0; sub < 2; sub++) {
            uint32_t ahi[4][4], alo[4][4], bhi[2][4], blo[2][4];
            #pragma unroll
            for (int mt = 0; mt < 4; mt++) {
                int r = mw * 64 + mt * 16 + (lane & 15);
                int c = sub * 16 + ((lane >> 4) << 3);
                ldsm4(ahi[mt], sAh[cur] + r * 40 + c);
                ldsm4(alo[mt], sAl[cur] + r * 40 + c);
            }
            #pragma unroll
            for (int bt = 0; bt < 2; bt++) {
                int r = sub * 16 + (lane & 15);
                int c = nw * 32 + bt * 16 + ((lane >> 4) << 3);
                ldsm4t(bhi[bt], sBh[cur] + r * 136 + c);
                ldsm4t(blo[bt], sBl[cur] + r * 136 + c);
            }
            #pragma unroll
            for (int mt = 0; mt < 4; mt++)
                #pragma unroll
                for (int nt = 0; nt < 4; nt++) {
                    const uint32_t* bh = &bhi[nt >> 1][(nt & 1) * 2];
                    const uint32_t* bl = &blo[nt >> 1][(nt & 1) * 2];
                    mma16816(acc[mt][nt], ahi[mt], bh);
                    mma16816(acc[mt][nt], ahi[mt], bl);
                    mma16816(acc[mt][nt], alo[mt], bh);
                }
        }
        __syncthreads();
    }

    float scol[4][2];
    #pragma unroll
    for (int nt = 0; nt < 4; nt++) { scol[nt][0] = 0.f; scol[nt][1] = 0.f; }

    #pragma unroll
    for (int mt = 0; mt < 4; mt++) {
        int r = row0 + mw * 64 + mt * 16 + (lane >> 2);
        int b = r >> 13, n = r & 8191;
        #pragma unroll
        for (int nt = 0; nt < 4; nt++) {
            int c = col0 + nw * 32 + nt * 8 + ((lane & 3) << 1);
            float2 p0 = make_float2(acc[mt][nt][0], acc[mt][nt][1]);
            float2 p1 = make_float2(acc[mt][nt][2], acc[mt][nt][3]);
            if (c < 256) {                      // q
                int h = c >> 5, e = c & 31;
                size_t o0 = ((size_t)(b * 8 + h) * NSEQ + n) * 32 + e;
                __nv_bfloat16 h0, h1, l0, l1;
                split_bf(p0.x, h0, l0); split_bf(p0.y, h1, l1);
                *(__nv_bfloat162*)(g_qhi + o0) = __halves2bfloat162(h0, h1);
                *(__nv_bfloat162*)(g_qlo + o0) = __halves2bfloat162(l0, l1);
                split_bf(p1.x, h0, l0); split_bf(p1.y, h1, l1);
                *(__nv_bfloat162*)(g_qhi + o0 + 256) = __halves2bfloat162(h0, h1);
                *(__nv_bfloat162*)(g_qlo + o0 + 256) = __halves2bfloat162(l0, l1);
            } else if (c < 512) {               // exp(k)
                int ck = c - 256;
                int h = ck >> 5, e = ck & 31;
                float e00 = __expf(p0.x), e01 = __expf(p0.y);
                float e10 = __expf(p1.x), e11 = __expf(p1.y);
                scol[nt][0] += e00 + e10;
                scol[nt][1] += e01 + e11;
                size_t o0 = ((size_t)(b * 8 + h) * NSEQ + n) * 32 + e;
                __nv_bfloat16 h0, h1, l0, l1;
                split_bf(e00, h0, l0); split_bf(e01, h1, l1);
                *(__nv_bfloat162*)(g_ehi + o0) = __halves2bfloat162(h0, h1);
                *(__nv_bfloat162*)(g_elo + o0) = __halves2bfloat162(l0, l1);
                split_bf(e10, h0, l0); split_bf(e11, h1, l1);
                *(__nv_bfloat162*)(g_ehi + o0 + 256) = __halves2bfloat162(h0, h1);
                *(__nv_bfloat162*)(g_elo + o0 + 256) = __halves2bfloat162(l0, l1);
            } else {                            // v
                int cv = c - 512;
                __nv_bfloat16 h0, h1, l0, l1;
                split_bf(p0.x, h0, l0); split_bf(p0.y, h1, l1);
                *(__nv_bfloat162*)(g_vhi + (size_t)r * 256 + cv) = __halves2bfloat162(h0, h1);
                *(__nv_bfloat162*)(g_vlo + (size_t)r * 256 + cv) = __halves2bfloat162(l0, l1);
                split_bf(p1.x, h0, l0); split_bf(p1.y, h1, l1);
                *(__nv_bfloat162*)(g_vhi + (size_t)(r + 8) * 256 + cv) = __halves2bfloat162(h0, h1);
                *(__nv_bfloat162*)(g_vlo + (size_t)(r + 8) * 256 + cv) = __halves2bfloat162(l0, l1);
            }
        }
    }

    // ek blocks: reduce column sums over the block's 256 rows -> g_Sp2
    if (col0 == 256 || col0 == 384) {
        __syncthreads();
        float* sS = (float*)sm;  // [128 cols][32 groups]
        int grp = mw * 8 + (lane >> 2);
        #pragma unroll
        for (int nt = 0; nt < 4; nt++)
            #pragma unroll
            for (int p = 0; p < 2; p++) {
                int ckL = nw * 32 + nt * 8 + ((lane & 3) << 1) + p;
                sS[ckL * 32 + grp] = scol[nt][p];
            }
        __syncthreads();
        if (tid < 128) {
            float s = 0.f;
            #pragma unroll
            for (int g = 0; g < 32; g++) s += sS[tid * 32 + g];
            g_Sp2[(size_t)blockIdx.y * 256 + (col0 - 256) + tid] = s;
        }
    }
}

// ============================================================================
// K2: tensor-core stats. grid (64 bh, 8 segs of 1024 rows), 256 thr.
// Warp w: rows w*128..+128, per-warp 2-stage cp.async, mma over k16 steps.
// A-frag = ek^T (ldmatrix.trans of [i][d] tile), B-frag = q ([i][e], k-major).
// ============================================================================
__global__ __launch_bounds__(256) void k_stats() {
    extern __shared__ __nv_bfloat16 sms[];
    int bh = blockIdx.x, seg = blockIdx.y;
    int tid = threadIdx.x, warp = tid >> 5, lane = tid & 31;

    __nv_bfloat16* wbase = sms + warp * 5120;        // 2 stages x 2560 halves
    const size_t rowbase = ((size_t)bh * NSEQ + seg * SSEG + warp * 128) * 32;
    const __nv_bfloat16* Qh = g_qhi + rowbase;
    const __nv_bfloat16* Ql = g_qlo + rowbase;
    const __nv_bfloat16* Eh = g_ehi + rowbase;
    const __nv_bfloat16* El = g_elo + rowbase;

    const int lr = lane & 15;          // tile row this lane loads
    const int lc = (lane >> 4) * 16;   // halves offset (2 cp16 per lane per tile)

    auto prefetch = [&](int st, int s) {
        __nv_bfloat16* sb = wbase + st * 2560;
        size_t src = (size_t)(s * 16 + lr) * 32 + lc;
        cp16(sb +    0 + lr * 40 + lc, Qh + src);
        cp16(sb +    8 + lr * 40 + lc, Qh + src + 8);
        cp16(sb +  640 + lr * 40 + lc, Ql + src);
        cp16(sb +  648 + lr * 40 + lc, Ql + src + 8);
        cp16(sb + 1280 + lr * 40 + lc, Eh + src);
        cp16(sb + 1288 + lr * 40 + lc, Eh + src + 8);
        cp16(sb + 1920 + lr * 40 + lc, El + src);
        cp16(sb + 1928 + lr * 40 + lc, El + src + 8);
        cp_commit();
    };

    float acc[2][4][4];
    #pragma unroll
    for (int dt = 0; dt < 2; dt++)
        #pragma unroll
        for (int nt = 0; nt < 4; nt++)
            #pragma unroll
            for (int i = 0; i < 4; i++) acc[dt][nt][i] = 0.f;

    const int ar = (lane & 7) | ((lane & 16) >> 1);  // trans-A row
    const int ac = lane & 8;                          // trans-A col add
    const int br = lane & 15;
    const int bc = (lane >> 4) << 3;

    prefetch(0, 0);
    for (int s = 0; s < 8; s++) {
        if (s < 7) { prefetch((s + 1) & 1, s + 1); cp_wait<1>(); }
        else cp_wait<0>();
        __syncwarp();
        __nv_bfloat16* sb = wbase + (s & 1) * 2560;
        uint32_t Ahf[2][4], Alf[2][4], Bhf[2][4], Blf[2][4];
        #pragma unroll
        for (int dt = 0; dt < 2; dt++) {
            int c = dt * 16 + ac;
            ldsm4t(Ahf[dt], sb + 1280 + ar * 40 + c);
            ldsm4t(Alf[dt], sb + 1920 + ar * 40 + c);
        }
        #pragma unroll
        for (int et = 0; et < 2; et++) {
            int c = et * 16 + bc;
            ldsm4t(Bhf[et], sb +   0 + br * 40 + c);
            ldsm4t(Blf[et], sb + 640 + br * 40 + c);
        }
        #pragma unroll
        for (int dt = 0; dt < 2; dt++)
            #pragma unroll
            for (int nt = 0; nt < 4; nt++) {
                const uint32_t* bh = &Bhf[nt >> 1][(nt & 1) * 2];
                const uint32_t* bl = &Blf[nt >> 1][(nt & 1) * 2];
                mma16816(acc[dt][nt], Ahf[dt], bh);
                mma16816(acc[dt][nt], Ahf[dt], bl);
                mma16816(acc[dt][nt], Alf[dt], bh);
            }
        __syncwarp();
    }

    // reduce 8 warp-partials -> g_Apart
    float* red = (float*)(sms + 8 * 5120);           // [8][1024]
    int gr = lane >> 2, tc = lane & 3;
    #pragma unroll
    for (int dt = 0; dt < 2; dt++)
        #pragma unroll
        for (int nt = 0; nt < 4; nt++) {
            int d0 = dt * 16 + gr, e0 = nt * 8 + tc * 2;
            red[warp * 1024 + d0 * 32 + e0]           = acc[dt][nt][0];
            red[warp * 1024 + d0 * 32 + e0 + 1]       = acc[dt][nt][1];
            red[warp * 1024 + (d0 + 8) * 32 + e0]     = acc[dt][nt][2];
            red[warp * 1024 + (d0 + 8) * 32 + e0 + 1] = acc[dt][nt][3];
        }
    __syncthreads();
    float* ap = g_Apart + ((size_t)bh * NSEG + seg) * 1024;
    #pragma unroll
    for (int c = 0; c < 4; c++) {
        int idx = tid * 4 + c;
        float s = 0.f;
        #pragma unroll
        for (int w = 0; w < 8; w++) s += red[w * 1024 + idx];
        ap[idx] = s;
    }
}

// ============================================================================
// K3: combine -> A[bh][d][e] = SCALE * sum(Apart)/sumExp_d
// ============================================================================
__global__ __launch_bounds__(256) void k_combine() {
    int bh = blockIdx.x, tid = threadIdx.x;
    int b = bh >> 3, h = bh & 7;
    __shared__ float sinv[32];
    if (tid < 32) {
        float s = 0.f;
        for (int rb = 0; rb < 32; rb++)
            s += g_Sp2[(size_t)(b * 32 + rb) * 256 + h * 32 + tid];
        sinv[tid] = SCALE_ / s;
    }
    __syncthreads();
    for (int idx = tid; idx < 1024; idx += 256) {
        float a = 0.f;
        for (int seg = 0; seg < NSEG; seg++)
            a += g_Apart[((size_t)bh * NSEG + seg) * 1024 + idx];
        g_A[bh * 1024 + idx] = a * sinv[idx >> 5];
    }
}

// ============================================================================
// K3b: W2[bh][l*32+d][c] = sum_e A[bh][d][e] * Wout[l*32+e][c], split to bf16
// ============================================================================
__global__ __launch_bounds__(256) void k_w2(const float* __restrict__ Wout) {
    __shared__ float A_s[1024];
    __shared__ float Wsh[32 * 256];
    int bh = blockIdx.x, tid = threadIdx.x;
    for (int i = tid; i < 1024; i += 256) A_s[i] = g_A[bh * 1024 + i];
    for (int l = 0; l < 8; l++) {
        __syncthreads();
        const float4* wsrc = (const float4*)(Wout + l * 32 * 256);
        float4* wdst = (float4*)Wsh;
        for (int i = tid; i < 2048; i += 256) wdst[i] = wsrc[i];
        __syncthreads();
        int c = tid;
        for (int d = 0; d < 32; d++) {
            float s = 0.f;
            #pragma unroll
            for (int e = 0; e < 32; e++) s += A_s[d * 32 + e] * Wsh[e * 256 + c];
            __nv_bfloat16 hi, lo; split_bf(s, hi, lo);
            size_t off = (size_t)bh * 65536 + (size_t)(l * 32 + d) * 256 + c;
            g_w2hi[off] = hi; g_w2lo[off] = lo;
        }
    }
}

// ============================================================================
// K4: per (b,h): Y[1024x256] = Vcat @ W2 + bias, LayerNorm, write out.
// ============================================================================
#define K4_STG 22016
__global__ __launch_bounds__(512, 1) void k4_out(const float* __restrict__ bout,
                                                 const float* __restrict__ gamma,
                                                 const float* __restrict__ beta,
                                                 float* __restrict__ out) {
    extern __shared__ __nv_bfloat16 sm[];
    const int tid = threadIdx.x, lane = tid & 31, warp = tid >> 5;
    const int mw = warp >> 3, nw = warp & 7;
    const int bh = blockIdx.y, b = bh >> 3, h = bh & 7;
    const int t0 = blockIdx.x * 64;

    __nv_bfloat16 *sAh[3], *sAl[3], *sBh[3], *sBl[3];
    #pragma unroll
    for (int s = 0; s < 3; s++) {
        __nv_bfloat16* base = sm + s * K4_STG;
        sAh[s] = base; sAl[s] = base + 2560;
        sBh[s] = base + 5120; sBl[s] = base + 13568;
    }

    auto load_stage = [&](int s, int kt) {
        {
            int ch = tid & 255; int ar = ch >> 2; int ac = (ch & 3) * 8;
            const size_t go = ((size_t)(b * 8192) + (size_t)(t0 + ar) * 8 + kt) * 256 + h * 32 + ac;
            if (tid < 256) cp16(sAh[s] + ar * 40 + ac, g_vhi + go);
            else           cp16(sAl[s] + ar * 40 + ac, g_vlo + go);
        }
        #pragma unroll
        for (int i = 0; i < 2; i++) {
            int ch = tid * 2 + i; int br = ch >> 5; int bc = (ch & 31) * 8;
            const size_t go = (size_t)bh * 65536 + (size_t)(kt * 32 + br) * 256 + bc;
            cp16(sBh[s] + br * 264 + bc, g_w2hi + go);
            cp16(sBl[s] + br * 264 + bc, g_w2lo + go);
        }
        cp_commit();
    };

    float acc[2][4][4];
    #pragma unroll
    for (int mt = 0; mt < 2; mt++)
        #pragma unroll
        for (int nt = 0; nt < 4; nt++)
            #pragma unroll
            for (int i = 0; i < 4; i++) acc[mt][nt][i] = 0.f;

    load_stage(0, 0);
    load_stage(1, 1);
    for (int kt = 0; kt < 8; kt++) {
        int cur = kt % 3;
        if (kt < 6)       { load_stage((kt + 2) % 3, kt + 2); cp_wait<2>(); }
        else if (kt == 6) cp_wait<1>();
        else              cp_wait<0>();
        __syncthreads();
        #pragma unroll
        for (int sub = 0; sub < 2; sub++) {
            uint32_t ahi[2][4], alo[2][4], bhi[2][4], blo[2][4];
            #pragma unroll
            for (int mt = 0; mt < 2; mt++) {
                int r = mw * 32 + mt * 16 + (lane & 15);
                int c = sub * 16 + ((lane >> 4) << 3);
                ldsm4(ahi[mt], sAh[cur] + r * 40 + c);
                ldsm4(alo[mt], sAl[cur] + r * 40 + c);
            }
            #pragma unroll
            for (int bt = 0; bt < 2; bt++) {
                int r = sub * 16 + (lane & 15);
                int c = nw * 32 + bt * 16 + ((lane >> 4) << 3);
                ldsm4t(bhi[bt], sBh[cur] + r * 264 + c);
                ldsm4t(blo[bt], sBl[cur] + r * 264 + c);
            }
            #pragma unroll
            for (int mt = 0; mt < 2; mt++)
                #pragma unroll
                for (int nt = 0; nt < 4; nt++) {
                    const uint32_t* bhp = &bhi[nt >> 1][(nt & 1) * 2];
                    const uint32_t* blp = &blo[nt >> 1][(nt & 1) * 2];
                    mma16816(acc[mt][nt], ahi[mt], bhp);
                    mma16816(acc[mt][nt], ahi[mt], blp);
                    mma16816(acc[mt][nt], alo[mt], bhp);
                }
        }
        __syncthreads();
    }

    // ---------------- epilogue: bias + LayerNorm -----------------------------
    float* red   = (float*)sm;
    float* sred  = red;            // [64][8]
    float* s2red = red + 512;      // [64][8]
    float* mus   = red + 1024;     // [64]
    float* rst   = red + 1088;     // [64]

    float bo[4][2];
    #pragma unroll
    for (int nt = 0; nt < 4; nt++) {
        int c = nw * 32 + nt * 8 + ((lane & 3) << 1);
        float2 bv = *(const float2*)(bout + c);
        bo[nt][0] = bv.x; bo[nt][1] = bv.y;
    }

    #pragma unroll
    for (int mt = 0; mt < 2; mt++)
        #pragma unroll
        for (int half = 0; half < 2; half++) {
            float s = 0.f, s2 = 0.f;
            #pragma unroll
            for (int nt = 0; nt < 4; nt++) {
                float v0 = acc[mt][nt][half * 2 + 0] + bo[nt][0];
                float v1 = acc[mt][nt][half * 2 + 1] + bo[nt][1];
                s += v0 + v1; s2 += v0 * v0 + v1 * v1;
            }
            s  += __shfl_xor_sync(0xffffffffu, s, 1);
            s  += __shfl_xor_sync(0xffffffffu, s, 2);
            s2 += __shfl_xor_sync(0xffffffffu, s2, 1);
            s2 += __shfl_xor_sync(0xffffffffu, s2, 2);
            if ((lane & 3) == 0) {
                int rl = mw * 32 + mt * 16 + (lane >> 2) + half * 8;
                sred[rl * 8 + nw] = s;
                s2red[rl * 8 + nw] = s2;
            }
        }
    __syncthreads();
    if (tid < 64) {
        float s = 0.f, s2 = 0.f;
        #pragma unroll
        for (int w = 0; w < 8; w++) { s += sred[tid * 8 + w]; s2 += s2red[tid * 8 + w]; }
        float mu = s * (1.f / 256.f);
        float var = s2 * (1.f / 256.f) - mu * mu;
        mus[tid] = mu;
        rst[tid] = rsqrtf(var + LN_EPS);
    }
    __syncthreads();

    #pragma unroll
    for (int mt = 0; mt < 2; mt++)
        #pragma unroll
        for (int half = 0; half < 2; half++) {
            int rl = mw * 32 + mt * 16 + (lane >> 2) + half * 8;
            float mu = mus[rl], rs = rst[rl];
            size_t orow = ((size_t)b * 8192 + (size_t)h * 1024 + t0 + rl) * 256;
            #pragma unroll
            for (int nt = 0; nt < 4; nt++) {
                int c = nw * 32 + nt * 8 + ((lane & 3) << 1);
                float2 g = *(const float2*)(gamma + c);
                float2 be = *(const float2*)(beta + c);
                float v0 = acc[mt][nt][half * 2 + 0] + bo[nt][0];
                float v1 = acc[mt][nt][half * 2 + 1] + bo[nt][1];
                float2 o = make_float2((v0 - mu) * rs * g.x + be.x,
                                       (v1 - mu) * rs * g.y + be.y);
                *(float2*)(out + orow + c) = o;
            }
        }
}

// ============================================================================
extern "C" void kernel_launch(void* const* d_in, const int* in_sizes, int n_in,
                              void* d_out, int out_size) {
    const float* x     = (const float*)d_in[0];
    const float* Wqkv  = (const float*)d_in[1];
    const float* Wout  = (const float*)d_in[2];
    const float* bout  = (const float*)d_in[3];
    const float* gamma = (const float*)d_in[4];
    const float* beta  = (const float*)d_in[5];
    float* out = (float*)d_out;

    const int statsSmem = 8 * 5120 * 2 + 8 * 1024 * 4;   // tiles + reduction
    cudaFuncSetAttribute(k1_gemm, cudaFuncAttributeMaxDynamicSharedMemorySize, 3 * K1_STG * 2);
    cudaFuncSetAttribute(k_stats, cudaFuncAttributeMaxDynamicSharedMemorySize, statsSmem);
    cudaFuncSetAttribute(k4_out,  cudaFuncAttributeMaxDynamicSharedMemorySize, 3 * K4_STG * 2);

    k_split_x<<<16384, 256>>>(x);
    k_split_w<<<192, 256>>>(Wqkv);
    k1_gemm<<<dim3(6, 256), 512, 3 * K1_STG * 2>>>();
    k_stats<<<dim3(64, NSEG), 256, statsSmem>>>();
    k_combine<<<64, 256>>>();
    k_w2<<<64, 256>>>(Wout);
    k4_out<<<dim3(16, 64), 512, 3 * K4_STG * 2>>>(bout, gamma, beta, out);
}

// round 8
// speedup vs baseline: 5.5117x; 1.8327x over previous
#include <cuda_runtime.h>
#include <cuda_fp16.h>
#include <math.h>
#include <stdint.h>

#define B_      8
#define NSEQ    8192
#define NROWS   65536
#define SCALE_  0.0625f
#define LN_EPS  1e-5f
#define NSEG    8
#define SSEG    1024

// ---------------- scratch ----------------------------------------------------
__device__ __half g_qh[(size_t)64 * NSEQ * 32];
__device__ __half g_eh[(size_t)64 * NSEQ * 32];
__device__ __half g_xh[(size_t)NROWS * 256];
__device__ __half g_wh[256 * 768];
__device__ __half g_vh[(size_t)NROWS * 256];
__device__ float g_Apart[64 * NSEG * 1024];
__device__ float g_Sp2[256 * 256];            // [rowblk(256 rows)][k-col]
__device__ float g_A[64 * 1024];
__device__ __half g_w2h[64 * 256 * 256];

// ---------------- PTX helpers ------------------------------------------------
__device__ __forceinline__ uint32_t smem_u32(const void* p) {
    return (uint32_t)__cvta_generic_to_shared(p);
}
__device__ __forceinline__ void cp16(void* dst, const void* src) {
    asm volatile("cp.async.cg.shared.global [%0], [%1], 16;\n"
                 :: "r"(smem_u32(dst)), "l"(src));
}
__device__ __forceinline__ void cp_commit() { asm volatile("cp.async.commit_group;\n"); }
template<int N> __device__ __forceinline__ void cp_wait() {
    asm volatile("cp.async.wait_group %0;\n" :: "n"(N));
}
__device__ __forceinline__ void ldsm4(uint32_t (&r)[4], const void* p) {
    asm volatile("ldmatrix.sync.aligned.m8n8.x4.shared.b16 {%0,%1,%2,%3}, [%4];"
                 : "=r"(r[0]), "=r"(r[1]), "=r"(r[2]), "=r"(r[3]) : "r"(smem_u32(p)));
}
__device__ __forceinline__ void ldsm4t(uint32_t (&r)[4], const void* p) {
    asm volatile("ldmatrix.sync.aligned.m8n8.x4.trans.shared.b16 {%0,%1,%2,%3}, [%4];"
                 : "=r"(r[0]), "=r"(r[1]), "=r"(r[2]), "=r"(r[3]) : "r"(smem_u32(p)));
}
__device__ __forceinline__ void mma16816h(float (&d)[4], const uint32_t (&a)[4], const uint32_t* b) {
    asm volatile("mma.sync.aligned.m16n8k16.row.col.f32.f16.f16.f32 "
                 "{%0,%1,%2,%3}, {%4,%5,%6,%7}, {%8,%9}, {%0,%1,%2,%3};"
                 : "+f"(d[0]), "+f"(d[1]), "+f"(d[2]), "+f"(d[3])
                 : "r"(a[0]), "r"(a[1]), "r"(a[2]), "r"(a[3]), "r"(b[0]), "r"(b[1]));
}

// ============================================================================
// convert kernels: fp32 -> fp16
// ============================================================================
__global__ __launch_bounds__(256) void k_cvt_x(const float* __restrict__ x) {
    size_t i = ((size_t)blockIdx.x * 256 + threadIdx.x) * 4;
    float4 v = *(const float4*)(x + i);
    *(__half2*)(g_xh + i)     = __halves2half2(__float2half(v.x), __float2half(v.y));
    *(__half2*)(g_xh + i + 2) = __halves2half2(__float2half(v.z), __float2half(v.w));
}
__global__ __launch_bounds__(256) void k_cvt_w(const float* __restrict__ W) {
    int idx = blockIdx.x * 256 + threadIdx.x;
    g_wh[idx] = __float2half(W[idx]);
}

// ============================================================================
// K1: qkv = x @ Wqkv, fp16 mma.  BM=256, BN=128, BK=32, 512 thr, 3 stages.
// grid (6 colblk fastest, 256 rowblk).  Epilogue routes q/ek/v + k col sums.
// stage halves: A 256*40 + B 32*136 = 14592
// ============================================================================
#define K1_STG 14592
__global__ __launch_bounds__(512, 1) void k1_gemm() {
    extern __shared__ __half sm[];
    const int tid = threadIdx.x, lane = tid & 31, warp = tid >> 5;
    const int mw = warp >> 2, nw = warp & 3;
    const int row0 = blockIdx.y * 256, col0 = blockIdx.x * 128;

    __half *sA[3], *sB[3];
    #pragma unroll
    for (int s = 0; s < 3; s++) {
        sA[s] = sm + s * K1_STG;
        sB[s] = sm + s * K1_STG + 10240;
    }

    auto load_stage = [&](int s, int kt) {
        const int k0 = kt * 32;
        #pragma unroll
        for (int i = 0; i < 2; i++) {
            int ch = tid * 2 + i; int ar = ch >> 2; int ac = (ch & 3) * 8;
            cp16(sA[s] + ar * 40 + ac, g_xh + (size_t)(row0 + ar) * 256 + k0 + ac);
        }
        {
            int br = tid >> 4; int bc = (tid & 15) * 8;
            cp16(sB[s] + br * 136 + bc, g_wh + (size_t)(k0 + br) * 768 + col0 + bc);
        }
        cp_commit();
    };

    float acc[4][4][4];
    #pragma unroll
    for (int mt = 0; mt < 4; mt++)
        #pragma unroll
        for (int nt = 0; nt < 4; nt++)
            #pragma unroll
            for (int i = 0; i < 4; i++) acc[mt][nt][i] = 0.f;

    load_stage(0, 0);
    load_stage(1, 1);
    for (int kt = 0; kt < 8; kt++) {
        int cur = kt % 3;
        if (kt < 6)       { load_stage((kt + 2) % 3, kt + 2); cp_wait<2>(); }
        else if (kt == 6) cp_wait<1>();
        else              cp_wait<0>();
        __syncthreads();
        #pragma unroll
        for (int sub = 0; sub < 2; sub++) {
            uint32_t af[4][4], bf[2][4];
            #pragma unroll
            for (int mt = 0; mt < 4; mt++) {
                int r = mw * 64 + mt * 16 + (lane & 15);
                int c = sub * 16 + ((lane >> 4) << 3);
                ldsm4(af[mt], sA[cur] + r * 40 + c);
            }
            #pragma unroll
            for (int bt = 0; bt < 2; bt++) {
                int r = sub * 16 + (lane & 15);
                int c = nw * 32 + bt * 16 + ((lane >> 4) << 3);
                ldsm4t(bf[bt], sB[cur] + r * 136 + c);
            }
            #pragma unroll
            for (int mt = 0; mt < 4; mt++)
                #pragma unroll
                for (int nt = 0; nt < 4; nt++)
                    mma16816h(acc[mt][nt], af[mt], &bf[nt >> 1][(nt & 1) * 2]);
        }
        __syncthreads();
    }

    float scol[4][2];
    #pragma unroll
    for (int nt = 0; nt < 4; nt++) { scol[nt][0] = 0.f; scol[nt][1] = 0.f; }

    #pragma unroll
    for (int mt = 0; mt < 4; mt++) {
        int r = row0 + mw * 64 + mt * 16 + (lane >> 2);
        int b = r >> 13, n = r & 8191;
        #pragma unroll
        for (int nt = 0; nt < 4; nt++) {
            int c = col0 + nw * 32 + nt * 8 + ((lane & 3) << 1);
            float2 p0 = make_float2(acc[mt][nt][0], acc[mt][nt][1]);
            float2 p1 = make_float2(acc[mt][nt][2], acc[mt][nt][3]);
            if (c < 256) {                      // q
                int h = c >> 5, e = c & 31;
                size_t o0 = ((size_t)(b * 8 + h) * NSEQ + n) * 32 + e;
                *(__half2*)(g_qh + o0)       = __halves2half2(__float2half(p0.x), __float2half(p0.y));
                *(__half2*)(g_qh + o0 + 256) = __halves2half2(__float2half(p1.x), __float2half(p1.y));
            } else if (c < 512) {               // exp(k)
                int ck = c - 256;
                int h = ck >> 5, e = ck & 31;
                float e00 = __expf(p0.x), e01 = __expf(p0.y);
                float e10 = __expf(p1.x), e11 = __expf(p1.y);
                scol[nt][0] += e00 + e10;
                scol[nt][1] += e01 + e11;
                size_t o0 = ((size_t)(b * 8 + h) * NSEQ + n) * 32 + e;
                *(__half2*)(g_eh + o0)       = __halves2half2(__float2half(e00), __float2half(e01));
                *(__half2*)(g_eh + o0 + 256) = __halves2half2(__float2half(e10), __float2half(e11));
            } else {                            // v
                int cv = c - 512;
                *(__half2*)(g_vh + (size_t)r * 256 + cv) =
                    __halves2half2(__float2half(p0.x), __float2half(p0.y));
                *(__half2*)(g_vh + (size_t)(r + 8) * 256 + cv) =
                    __halves2half2(__float2half(p1.x), __float2half(p1.y));
            }
        }
    }

    if (col0 == 256 || col0 == 384) {
        __syncthreads();
        float* sS = (float*)sm;  // [128 cols][32 groups]
        int grp = mw * 8 + (lane >> 2);
        #pragma unroll
        for (int nt = 0; nt < 4; nt++)
            #pragma unroll
            for (int p = 0; p < 2; p++) {
                int ckL = nw * 32 + nt * 8 + ((lane & 3) << 1) + p;
                sS[ckL * 32 + grp] = scol[nt][p];
            }
        __syncthreads();
        if (tid < 128) {
            float s = 0.f;
            #pragma unroll
            for (int g = 0; g < 32; g++) s += sS[tid * 32 + g];
            g_Sp2[(size_t)blockIdx.y * 256 + (col0 - 256) + tid] = s;
        }
    }
}

// ============================================================================
// K2: tensor-core stats, fp16. grid (64 bh, 8 segs), 256 thr.
// per-warp 2-stage: stage = [Q 16x40][E 16x40] = 1280 halves.
// ============================================================================
__global__ __launch_bounds__(256) void k_stats() {
    extern __shared__ __half sms[];
    int bh = blockIdx.x, seg = blockIdx.y;
    int tid = threadIdx.x, warp = tid >> 5, lane = tid & 31;

    __half* wbase = sms + warp * 2560;
    const size_t rowbase = ((size_t)bh * NSEQ + seg * SSEG + warp * 128) * 32;
    const __half* Q = g_qh + rowbase;
    const __half* E = g_eh + rowbase;

    const int lr = lane & 15;
    const int lc = (lane >> 4) * 16;

    auto prefetch = [&](int st, int s) {
        __half* sb = wbase + st * 1280;
        size_t src = (size_t)(s * 16 + lr) * 32 + lc;
        cp16(sb +   0 + lr * 40 + lc, Q + src);
        cp16(sb +   8 + lr * 40 + lc, Q + src + 8);
        cp16(sb + 640 + lr * 40 + lc, E + src);
        cp16(sb + 648 + lr * 40 + lc, E + src + 8);
        cp_commit();
    };

    float acc[2][4][4];
    #pragma unroll
    for (int dt = 0; dt < 2; dt++)
        #pragma unroll
        for (int nt = 0; nt < 4; nt++)
            #pragma unroll
            for (int i = 0; i < 4; i++) acc[dt][nt][i] = 0.f;

    const int ar = (lane & 7) | ((lane & 16) >> 1);
    const int ac = lane & 8;
    const int br = lane & 15;
    const int bc = (lane >> 4) << 3;

    prefetch(0, 0);
    for (int s = 0; s < 8; s++) {
        if (s < 7) { prefetch((s + 1) & 1, s + 1); cp_wait<1>(); }
        else cp_wait<0>();
        __syncwarp();
        __half* sb = wbase + (s & 1) * 1280;
        uint32_t Af[2][4], Bf[2][4];
        #pragma unroll
        for (int dt = 0; dt < 2; dt++)
            ldsm4t(Af[dt], sb + 640 + ar * 40 + dt * 16 + ac);
        #pragma unroll
        for (int et = 0; et < 2; et++)
            ldsm4t(Bf[et], sb + br * 40 + et * 16 + bc);
        #pragma unroll
        for (int dt = 0; dt < 2; dt++)
            #pragma unroll
            for (int nt = 0; nt < 4; nt++)
                mma16816h(acc[dt][nt], Af[dt], &Bf[nt >> 1][(nt & 1) * 2]);
        __syncwarp();
    }

    float* red = (float*)(sms + 8 * 2560);
    int gr = lane >> 2, tc = lane & 3;
    #pragma unroll
    for (int dt = 0; dt < 2; dt++)
        #pragma unroll
        for (int nt = 0; nt < 4; nt++) {
            int d0 = dt * 16 + gr, e0 = nt * 8 + tc * 2;
            red[warp * 1024 + d0 * 32 + e0]           = acc[dt][nt][0];
            red[warp * 1024 + d0 * 32 + e0 + 1]       = acc[dt][nt][1];
            red[warp * 1024 + (d0 + 8) * 32 + e0]     = acc[dt][nt][2];
            red[warp * 1024 + (d0 + 8) * 32 + e0 + 1] = acc[dt][nt][3];
        }
    __syncthreads();
    float* ap = g_Apart + ((size_t)bh * NSEG + seg) * 1024;
    #pragma unroll
    for (int c = 0; c < 4; c++) {
        int idx = tid * 4 + c;
        float s = 0.f;
        #pragma unroll
        for (int w = 0; w < 8; w++) s += red[w * 1024 + idx];
        ap[idx] = s;
    }
}

// ============================================================================
// K3: combine -> A[bh][d][e] = SCALE * sum(Apart)/sumExp_d
// ============================================================================
__global__ __launch_bounds__(256) void k_combine() {
    int bh = blockIdx.x, tid = threadIdx.x;
    int b = bh >> 3, h = bh & 7;
    __shared__ float sinv[32];
    if (tid < 32) {
        float s = 0.f;
        for (int rb = 0; rb < 32; rb++)
            s += g_Sp2[(size_t)(b * 32 + rb) * 256 + h * 32 + tid];
        sinv[tid] = SCALE_ / s;
    }
    __syncthreads();
    for (int idx = tid; idx < 1024; idx += 256) {
        float a = 0.f;
        for (int seg = 0; seg < NSEG; seg++)
            a += g_Apart[((size_t)bh * NSEG + seg) * 1024 + idx];
        g_A[bh * 1024 + idx] = a * sinv[idx >> 5];
    }
}

// ============================================================================
// K3b: W2[bh][l*32+d][c] = sum_e A[bh][d][e] * Wout[l*32+e][c] -> fp16
// ============================================================================
__global__ __launch_bounds__(256) void k_w2(const float* __restrict__ Wout) {
    __shared__ float A_s[1024];
    __shared__ float Wsh[32 * 256];
    int bh = blockIdx.x, tid = threadIdx.x;
    for (int i = tid; i < 1024; i += 256) A_s[i] = g_A[bh * 1024 + i];
    for (int l = 0; l < 8; l++) {
        __syncthreads();
        const float4* wsrc = (const float4*)(Wout + l * 32 * 256);
        float4* wdst = (float4*)Wsh;
        for (int i = tid; i < 2048; i += 256) wdst[i] = wsrc[i];
        __syncthreads();
        int c = tid;
        for (int d = 0; d < 32; d++) {
            float s = 0.f;
            #pragma unroll
            for (int e = 0; e < 32; e++) s += A_s[d * 32 + e] * Wsh[e * 256 + c];
            g_w2h[(size_t)bh * 65536 + (size_t)(l * 32 + d) * 256 + c] = __float2half(s);
        }
    }
}

// ============================================================================
// K4: per (b,h): Y[1024x256] = Vcat @ W2 + bias, LayerNorm, write out.
// BM=64, BN=256, BK=32, 512 thr, 3 stages. stage halves: A 64*40 + B 32*264 = 11008
// ============================================================================
#define K4_STG 11008
__global__ __launch_bounds__(512, 1) void k4_out(const float* __restrict__ bout,
                                                 const float* __restrict__ gamma,
                                                 const float* __restrict__ beta,
                                                 float* __restrict__ out) {
    extern __shared__ __half sm[];
    const int tid = threadIdx.x, lane = tid & 31, warp = tid >> 5;
    const int mw = warp >> 3, nw = warp & 7;
    const int bh = blockIdx.y, b = bh >> 3, h = bh & 7;
    const int t0 = blockIdx.x * 64;

    __half *sA[3], *sB[3];
    #pragma unroll
    for (int s = 0; s < 3; s++) {
        sA[s] = sm + s * K4_STG;
        sB[s] = sm + s * K4_STG + 2560;
    }

    auto load_stage = [&](int s, int kt) {
        if (tid < 256) {
            int ar = tid >> 2; int ac = (tid & 3) * 8;
            const size_t go = ((size_t)(b * 8192) + (size_t)(t0 + ar) * 8 + kt) * 256 + h * 32 + ac;
            cp16(sA[s] + ar * 40 + ac, g_vh + go);
        }
        #pragma unroll
        for (int i = 0; i < 2; i++) {
            int ch = tid * 2 + i; int br = ch >> 5; int bc = (ch & 31) * 8;
            const size_t go = (size_t)bh * 65536 + (size_t)(kt * 32 + br) * 256 + bc;
            cp16(sB[s] + br * 264 + bc, g_w2h + go);
        }
        cp_commit();
    };

    float acc[2][4][4];
    #pragma unroll
    for (int mt = 0; mt < 2; mt++)
        #pragma unroll
        for (int nt = 0; nt < 4; nt++)
            #pragma unroll
            for (int i = 0; i < 4; i++) acc[mt][nt][i] = 0.f;

    load_stage(0, 0);
    load_stage(1, 1);
    for (int kt = 0; kt < 8; kt++) {
        int cur = kt % 3;
        if (kt < 6)       { load_stage((kt + 2) % 3, kt + 2); cp_wait<2>(); }
        else if (kt == 6) cp_wait<1>();
        else              cp_wait<0>();
        __syncthreads();
        #pragma unroll
        for (int sub = 0; sub < 2; sub++) {
            uint32_t af[2][4], bf[2][4];
            #pragma unroll
            for (int mt = 0; mt < 2; mt++) {
                int r = mw * 32 + mt * 16 + (lane & 15);
                int c = sub * 16 + ((lane >> 4) << 3);
                ldsm4(af[mt], sA[cur] + r * 40 + c);
            }
            #pragma unroll
            for (int bt = 0; bt < 2; bt++) {
                int r = sub * 16 + (lane & 15);
                int c = nw * 32 + bt * 16 + ((lane >> 4) << 3);
                ldsm4t(bf[bt], sB[cur] + r * 264 + c);
            }
            #pragma unroll
            for (int mt = 0; mt < 2; mt++)
                #pragma unroll
                for (int nt = 0; nt < 4; nt++)
                    mma16816h(acc[mt][nt], af[mt], &bf[nt >> 1][(nt & 1) * 2]);
        }
        __syncthreads();
    }

    float* red   = (float*)sm;
    float* sred  = red;
    float* s2red = red + 512;
    float* mus   = red + 1024;
    float* rst   = red + 1088;

    float bo[4][2];
    #pragma unroll
    for (int nt = 0; nt < 4; nt++) {
        int c = nw * 32 + nt * 8 + ((lane & 3) << 1);
        float2 bv = *(const float2*)(bout + c);
        bo[nt][0] = bv.x; bo[nt][1] = bv.y;
    }

    #pragma unroll
    for (int mt = 0; mt < 2; mt++)
        #pragma unroll
        for (int half = 0; half < 2; half++) {
            float s = 0.f, s2 = 0.f;
            #pragma unroll
            for (int nt = 0; nt < 4; nt++) {
                float v0 = acc[mt][nt][half * 2 + 0] + bo[nt][0];
                float v1 = acc[mt][nt][half * 2 + 1] + bo[nt][1];
                s += v0 + v1; s2 += v0 * v0 + v1 * v1;
            }
            s  += __shfl_xor_sync(0xffffffffu, s, 1);
            s  += __shfl_xor_sync(0xffffffffu, s, 2);
            s2 += __shfl_xor_sync(0xffffffffu, s2, 1);
            s2 += __shfl_xor_sync(0xffffffffu, s2, 2);
            if ((lane & 3) == 0) {
                int rl = mw * 32 + mt * 16 + (lane >> 2) + half * 8;
                sred[rl * 8 + nw] = s;
                s2red[rl * 8 + nw] = s2;
            }
        }
    __syncthreads();
    if (tid < 64) {
        float s = 0.f, s2 = 0.f;
        #pragma unroll
        for (int w = 0; w < 8; w++) { s += sred[tid * 8 + w]; s2 += s2red[tid * 8 + w]; }
        float mu = s * (1.f / 256.f);
        float var = s2 * (1.f / 256.f) - mu * mu;
        mus[tid] = mu;
        rst[tid] = rsqrtf(var + LN_EPS);
    }
    __syncthreads();

    #pragma unroll
    for (int mt = 0; mt < 2; mt++)
        #pragma unroll
        for (int half = 0; half < 2; half++) {
            int rl = mw * 32 + mt * 16 + (lane >> 2) + half * 8;
            float mu = mus[rl], rs = rst[rl];
            size_t orow = ((size_t)b * 8192 + (size_t)h * 1024 + t0 + rl) * 256;
            #pragma unroll
            for (int nt = 0; nt < 4; nt++) {
                int c = nw * 32 + nt * 8 + ((lane & 3) << 1);
                float2 g = *(const float2*)(gamma + c);
                float2 be = *(const float2*)(beta + c);
                float v0 = acc[mt][nt][half * 2 + 0] + bo[nt][0];
                float v1 = acc[mt][nt][half * 2 + 1] + bo[nt][1];
                float2 o = make_float2((v0 - mu) * rs * g.x + be.x,
                                       (v1 - mu) * rs * g.y + be.y);
                *(float2*)(out + orow + c) = o;
            }
        }
}

// ============================================================================
extern "C" void kernel_launch(void* const* d_in, const int* in_sizes, int n_in,
                              void* d_out, int out_size) {
    const float* x     = (const float*)d_in[0];
    const float* Wqkv  = (const float*)d_in[1];
    const float* Wout  = (const float*)d_in[2];
    const float* bout  = (const float*)d_in[3];
    const float* gamma = (const float*)d_in[4];
    const float* beta  = (const float*)d_in[5];
    float* out = (float*)d_out;

    const int statsSmem = 8 * 2560 * 2 + 8 * 1024 * 4;
    cudaFuncSetAttribute(k1_gemm, cudaFuncAttributeMaxDynamicSharedMemorySize, 3 * K1_STG * 2);
    cudaFuncSetAttribute(k_stats, cudaFuncAttributeMaxDynamicSharedMemorySize, statsSmem);
    cudaFuncSetAttribute(k4_out,  cudaFuncAttributeMaxDynamicSharedMemorySize, 3 * K4_STG * 2);

    k_cvt_x<<<16384, 256>>>(x);
    k_cvt_w<<<768, 256>>>(Wqkv);
    k1_gemm<<<dim3(6, 256), 512, 3 * K1_STG * 2>>>();
    k_stats<<<dim3(64, NSEG), 256, statsSmem>>>();
    k_combine<<<64, 256>>>();
    k_w2<<<64, 256>>>(Wout);
    k4_out<<<dim3(16, 64), 512, 3 * K4_STG * 2>>>(bout, gamma, beta, out);
}

// round 9
// speedup vs baseline: 6.1197x; 1.1103x over previous
#include <cuda_runtime.h>
#include <cuda_fp16.h>
#include <math.h>
#include <stdint.h>

#define B_      8
#define NSEQ    8192
#define NROWS   65536
#define SCALE_  0.0625f
#define LN_EPS  1e-5f
#define NSEG    8
#define SSEG    1024

// ---------------- scratch ----------------------------------------------------
__device__ __half g_qh[(size_t)64 * NSEQ * 32];
__device__ __half g_eh[(size_t)64 * NSEQ * 32];
__device__ __half g_xh[(size_t)NROWS * 256];
__device__ __half g_wh[256 * 768];
__device__ __half g_vh[(size_t)NROWS * 256];
__device__ float g_Apart[64 * NSEG * 1024];
__device__ float g_Sp2[512 * 256];            // [rowblk(128 rows)][k-col]
__device__ __half g_w2h[64 * 256 * 256];

// ---------------- PTX helpers ------------------------------------------------
__device__ __forceinline__ uint32_t smem_u32(const void* p) {
    return (uint32_t)__cvta_generic_to_shared(p);
}
__device__ __forceinline__ void cp16(void* dst, const void* src) {
    asm volatile("cp.async.cg.shared.global [%0], [%1], 16;\n"
                 :: "r"(smem_u32(dst)), "l"(src));
}
__device__ __forceinline__ void cp_commit() { asm volatile("cp.async.commit_group;\n"); }
template<int N> __device__ __forceinline__ void cp_wait() {
    asm volatile("cp.async.wait_group %0;\n" :: "n"(N));
}
__device__ __forceinline__ void ldsm4(uint32_t (&r)[4], const void* p) {
    asm volatile("ldmatrix.sync.aligned.m8n8.x4.shared.b16 {%0,%1,%2,%3}, [%4];"
                 : "=r"(r[0]), "=r"(r[1]), "=r"(r[2]), "=r"(r[3]) : "r"(smem_u32(p)));
}
__device__ __forceinline__ void ldsm4t(uint32_t (&r)[4], const void* p) {
    asm volatile("ldmatrix.sync.aligned.m8n8.x4.trans.shared.b16 {%0,%1,%2,%3}, [%4];"
                 : "=r"(r[0]), "=r"(r[1]), "=r"(r[2]), "=r"(r[3]) : "r"(smem_u32(p)));
}
__device__ __forceinline__ void mma16816h(float (&d)[4], const uint32_t (&a)[4], const uint32_t* b) {
    asm volatile("mma.sync.aligned.m16n8k16.row.col.f32.f16.f16.f32 "
                 "{%0,%1,%2,%3}, {%4,%5,%6,%7}, {%8,%9}, {%0,%1,%2,%3};"
                 : "+f"(d[0]), "+f"(d[1]), "+f"(d[2]), "+f"(d[3])
                 : "r"(a[0]), "r"(a[1]), "r"(a[2]), "r"(a[3]), "r"(b[0]), "r"(b[1]));
}

// ============================================================================
// convert kernels: fp32 -> fp16
// ============================================================================
__global__ __launch_bounds__(256) void k_cvt_x(const float* __restrict__ x) {
    size_t i = ((size_t)blockIdx.x * 256 + threadIdx.x) * 4;
    float4 v = *(const float4*)(x + i);
    *(__half2*)(g_xh + i)     = __halves2half2(__float2half(v.x), __float2half(v.y));
    *(__half2*)(g_xh + i + 2) = __halves2half2(__float2half(v.z), __float2half(v.w));
}
__global__ __launch_bounds__(256) void k_cvt_w(const float* __restrict__ W) {
    int idx = blockIdx.x * 256 + threadIdx.x;
    g_wh[idx] = __float2half(W[idx]);
}

// ============================================================================
// K1: qkv = x @ Wqkv, fp16 mma.  BM=128, BN=128, BK=32, 256 thr, 3 stages,
// 2 CTAs/SM.  grid (6 colblk fastest, 512 rowblk).
// stage halves: A 128*40 + B 32*136 = 9472
// ============================================================================
#define K1_STG 9472
__global__ __launch_bounds__(256, 2) void k1_gemm() {
    extern __shared__ __half sm[];
    const int tid = threadIdx.x, lane = tid & 31, warp = tid >> 5;
    const int mw = warp >> 2, nw = warp & 3;
    const int row0 = blockIdx.y * 128, col0 = blockIdx.x * 128;

    __half *sA[3], *sB[3];
    #pragma unroll
    for (int s = 0; s < 3; s++) {
        sA[s] = sm + s * K1_STG;
        sB[s] = sm + s * K1_STG + 5120;
    }

    auto load_stage = [&](int s, int kt) {
        const int k0 = kt * 32;
        #pragma unroll
        for (int i = 0; i < 2; i++) {
            int id = tid * 2 + i; int ar = id >> 2; int ac = (id & 3) * 8;
            cp16(sA[s] + ar * 40 + ac, g_xh + (size_t)(row0 + ar) * 256 + k0 + ac);
        }
        #pragma unroll
        for (int i = 0; i < 2; i++) {
            int id = tid * 2 + i; int br = id >> 4; int bc = (id & 15) * 8;
            cp16(sB[s] + br * 136 + bc, g_wh + (size_t)(k0 + br) * 768 + col0 + bc);
        }
        cp_commit();
    };

    float acc[4][4][4];
    #pragma unroll
    for (int mt = 0; mt < 4; mt++)
        #pragma unroll
        for (int nt = 0; nt < 4; nt++)
            #pragma unroll
            for (int i = 0; i < 4; i++) acc[mt][nt][i] = 0.f;

    load_stage(0, 0);
    load_stage(1, 1);
    for (int kt = 0; kt < 8; kt++) {
        int cur = kt % 3;
        if (kt < 6)       { load_stage((kt + 2) % 3, kt + 2); cp_wait<2>(); }
        else if (kt == 6) cp_wait<1>();
        else              cp_wait<0>();
        __syncthreads();
        #pragma unroll
        for (int sub = 0; sub < 2; sub++) {
            uint32_t af[4][4], bf[2][4];
            #pragma unroll
            for (int mt = 0; mt < 4; mt++) {
                int r = mw * 64 + mt * 16 + (lane & 15);
                int c = sub * 16 + ((lane >> 4) << 3);
                ldsm4(af[mt], sA[cur] + r * 40 + c);
            }
            #pragma unroll
            for (int bt = 0; bt < 2; bt++) {
                int r = sub * 16 + (lane & 15);
                int c = nw * 32 + bt * 16 + ((lane >> 4) << 3);
                ldsm4t(bf[bt], sB[cur] + r * 136 + c);
            }
            #pragma unroll
            for (int mt = 0; mt < 4; mt++)
                #pragma unroll
                for (int nt = 0; nt < 4; nt++)
                    mma16816h(acc[mt][nt], af[mt], &bf[nt >> 1][(nt & 1) * 2]);
        }
        __syncthreads();
    }

    float scol[4][2];
    #pragma unroll
    for (int nt = 0; nt < 4; nt++) { scol[nt][0] = 0.f; scol[nt][1] = 0.f; }

    #pragma unroll
    for (int mt = 0; mt < 4; mt++) {
        int r = row0 + mw * 64 + mt * 16 + (lane >> 2);
        int b = r >> 13, n = r & 8191;
        #pragma unroll
        for (int nt = 0; nt < 4; nt++) {
            int c = col0 + nw * 32 + nt * 8 + ((lane & 3) << 1);
            float2 p0 = make_float2(acc[mt][nt][0], acc[mt][nt][1]);
            float2 p1 = make_float2(acc[mt][nt][2], acc[mt][nt][3]);
            if (c < 256) {                      // q
                int h = c >> 5, e = c & 31;
                size_t o0 = ((size_t)(b * 8 + h) * NSEQ + n) * 32 + e;
                *(__half2*)(g_qh + o0)       = __halves2half2(__float2half(p0.x), __float2half(p0.y));
                *(__half2*)(g_qh + o0 + 256) = __halves2half2(__float2half(p1.x), __float2half(p1.y));
            } else if (c < 512) {               // exp(k)
                int ck = c - 256;
                int h = ck >> 5, e = ck & 31;
                float e00 = __expf(p0.x), e01 = __expf(p0.y);
                float e10 = __expf(p1.x), e11 = __expf(p1.y);
                scol[nt][0] += e00 + e10;
                scol[nt][1] += e01 + e11;
                size_t o0 = ((size_t)(b * 8 + h) * NSEQ + n) * 32 + e;
                *(__half2*)(g_eh + o0)       = __halves2half2(__float2half(e00), __float2half(e01));
                *(__half2*)(g_eh + o0 + 256) = __halves2half2(__float2half(e10), __float2half(e11));
            } else {                            // v
                int cv = c - 512;
                *(__half2*)(g_vh + (size_t)r * 256 + cv) =
                    __halves2half2(__float2half(p0.x), __float2half(p0.y));
                *(__half2*)(g_vh + (size_t)(r + 8) * 256 + cv) =
                    __halves2half2(__float2half(p1.x), __float2half(p1.y));
            }
        }
    }

    if (col0 == 256 || col0 == 384) {
        __syncthreads();
        float* sS = (float*)sm;  // [128 cols][16 groups]
        int grp = mw * 8 + (lane >> 2);
        #pragma unroll
        for (int nt = 0; nt < 4; nt++)
            #pragma unroll
            for (int p = 0; p < 2; p++) {
                int ckL = nw * 32 + nt * 8 + ((lane & 3) << 1) + p;
                sS[ckL * 16 + grp] = scol[nt][p];
            }
        __syncthreads();
        if (tid < 128) {
            float s = 0.f;
            #pragma unroll
            for (int g = 0; g < 16; g++) s += sS[tid * 16 + g];
            g_Sp2[(size_t)blockIdx.y * 256 + (col0 - 256) + tid] = s;
        }
    }
}

// ============================================================================
// K2: tensor-core stats, fp16 (unchanged from R8).
// ============================================================================
__global__ __launch_bounds__(256) void k_stats() {
    extern __shared__ __half sms[];
    int bh = blockIdx.x, seg = blockIdx.y;
    int tid = threadIdx.x, warp = tid >> 5, lane = tid & 31;

    __half* wbase = sms + warp * 2560;
    const size_t rowbase = ((size_t)bh * NSEQ + seg * SSEG + warp * 128) * 32;
    const __half* Q = g_qh + rowbase;
    const __half* E = g_eh + rowbase;

    const int lr = lane & 15;
    const int lc = (lane >> 4) * 16;

    auto prefetch = [&](int st, int s) {
        __half* sb = wbase + st * 1280;
        size_t src = (size_t)(s * 16 + lr) * 32 + lc;
        cp16(sb +   0 + lr * 40 + lc, Q + src);
        cp16(sb +   8 + lr * 40 + lc, Q + src + 8);
        cp16(sb + 640 + lr * 40 + lc, E + src);
        cp16(sb + 648 + lr * 40 + lc, E + src + 8);
        cp_commit();
    };

    float acc[2][4][4];
    #pragma unroll
    for (int dt = 0; dt < 2; dt++)
        #pragma unroll
        for (int nt = 0; nt < 4; nt++)
            #pragma unroll
            for (int i = 0; i < 4; i++) acc[dt][nt][i] = 0.f;

    const int ar = (lane & 7) | ((lane & 16) >> 1);
    const int ac = lane & 8;
    const int br = lane & 15;
    const int bc = (lane >> 4) << 3;

    prefetch(0, 0);
    for (int s = 0; s < 8; s++) {
        if (s < 7) { prefetch((s + 1) & 1, s + 1); cp_wait<1>(); }
        else cp_wait<0>();
        __syncwarp();
        __half* sb = wbase + (s & 1) * 1280;
        uint32_t Af[2][4], Bf[2][4];
        #pragma unroll
        for (int dt = 0; dt < 2; dt++)
            ldsm4t(Af[dt], sb + 640 + ar * 40 + dt * 16 + ac);
        #pragma unroll
        for (int et = 0; et < 2; et++)
            ldsm4t(Bf[et], sb + br * 40 + et * 16 + bc);
        #pragma unroll
        for (int dt = 0; dt < 2; dt++)
            #pragma unroll
            for (int nt = 0; nt < 4; nt++)
                mma16816h(acc[dt][nt], Af[dt], &Bf[nt >> 1][(nt & 1) * 2]);
        __syncwarp();
    }

    float* red = (float*)(sms + 8 * 2560);
    int gr = lane >> 2, tc = lane & 3;
    #pragma unroll
    for (int dt = 0; dt < 2; dt++)
        #pragma unroll
        for (int nt = 0; nt < 4; nt++) {
            int d0 = dt * 16 + gr, e0 = nt * 8 + tc * 2;
            red[warp * 1024 + d0 * 32 + e0]           = acc[dt][nt][0];
            red[warp * 1024 + d0 * 32 + e0 + 1]       = acc[dt][nt][1];
            red[warp * 1024 + (d0 + 8) * 32 + e0]     = acc[dt][nt][2];
            red[warp * 1024 + (d0 + 8) * 32 + e0 + 1] = acc[dt][nt][3];
        }
    __syncthreads();
    float* ap = g_Apart + ((size_t)bh * NSEG + seg) * 1024;
    #pragma unroll
    for (int c = 0; c < 4; c++) {
        int idx = tid * 4 + c;
        float s = 0.f;
        #pragma unroll
        for (int w = 0; w < 8; w++) s += red[w * 1024 + idx];
        ap[idx] = s;
    }
}

// ============================================================================
// K3: fused combine + W2:  A[bh] = SCALE*sum(Apart)/sumExp_d;
//     W2[bh][l*32+d][c] = sum_e A[d][e] * Wout[l*32+e][c] -> fp16
// ============================================================================
__global__ __launch_bounds__(256) void k_cw(const float* __restrict__ Wout) {
    __shared__ float sinv[32];
    __shared__ float A_s[1024];
    __shared__ float Wsh[32 * 256];
    int bh = blockIdx.x, tid = threadIdx.x;
    int b = bh >> 3, h = bh & 7;
    if (tid < 32) {
        float s = 0.f;
        for (int rb = 0; rb < 64; rb++)
            s += g_Sp2[(size_t)(b * 64 + rb) * 256 + h * 32 + tid];
        sinv[tid] = SCALE_ / s;
    }
    __syncthreads();
    for (int idx = tid; idx < 1024; idx += 256) {
        float a = 0.f;
        for (int seg = 0; seg < NSEG; seg++)
            a += g_Apart[((size_t)bh * NSEG + seg) * 1024 + idx];
        A_s[idx] = a * sinv[idx >> 5];
    }
    for (int l = 0; l < 8; l++) {
        __syncthreads();
        const float4* wsrc = (const float4*)(Wout + l * 32 * 256);
        float4* wdst = (float4*)Wsh;
        for (int i = tid; i < 2048; i += 256) wdst[i] = wsrc[i];
        __syncthreads();
        int c = tid;
        for (int d = 0; d < 32; d++) {
            float s = 0.f;
            #pragma unroll
            for (int e = 0; e < 32; e++) s += A_s[d * 32 + e] * Wsh[e * 256 + c];
            g_w2h[(size_t)bh * 65536 + (size_t)(l * 32 + d) * 256 + c] = __float2half(s);
        }
    }
}

// ============================================================================
// K4: per (b,h): Y[1024x256] = Vcat @ W2 + bias, LayerNorm, write out.
// BM=128, BN=256, BK=32, 512 thr, 3 stages. stage halves: A 128*40 + B 32*264 = 13568
// ============================================================================
#define K4_STG 13568
__global__ __launch_bounds__(512, 1) void k4_out(const float* __restrict__ bout,
                                                 const float* __restrict__ gamma,
                                                 const float* __restrict__ beta,
                                                 float* __restrict__ out) {
    extern __shared__ __half sm[];
    const int tid = threadIdx.x, lane = tid & 31, warp = tid >> 5;
    const int mw = warp >> 3, nw = warp & 7;
    const int bh = blockIdx.y, b = bh >> 3, h = bh & 7;
    const int t0 = blockIdx.x * 128;

    __half *sA[3], *sB[3];
    #pragma unroll
    for (int s = 0; s < 3; s++) {
        sA[s] = sm + s * K4_STG;
        sB[s] = sm + s * K4_STG + 5120;
    }

    auto load_stage = [&](int s, int kt) {
        {
            int ar = tid >> 2; int ac = (tid & 3) * 8;
            const size_t go = ((size_t)(b * 8192) + (size_t)(t0 + ar) * 8 + kt) * 256 + h * 32 + ac;
            cp16(sA[s] + ar * 40 + ac, g_vh + go);
        }
        #pragma unroll
        for (int i = 0; i < 2; i++) {
            int id = tid * 2 + i; int br = id >> 5; int bc = (id & 31) * 8;
            const size_t go = (size_t)bh * 65536 + (size_t)(kt * 32 + br) * 256 + bc;
            cp16(sB[s] + br * 264 + bc, g_w2h + go);
        }
        cp_commit();
    };

    float acc[4][4][4];
    #pragma unroll
    for (int mt = 0; mt < 4; mt++)
        #pragma unroll
        for (int nt = 0; nt < 4; nt++)
            #pragma unroll
            for (int i = 0; i < 4; i++) acc[mt][nt][i] = 0.f;

    load_stage(0, 0);
    load_stage(1, 1);
    for (int kt = 0; kt < 8; kt++) {
        int cur = kt % 3;
        if (kt < 6)       { load_stage((kt + 2) % 3, kt + 2); cp_wait<2>(); }
        else if (kt == 6) cp_wait<1>();
        else              cp_wait<0>();
        __syncthreads();
        #pragma unroll
        for (int sub = 0; sub < 2; sub++) {
            uint32_t af[4][4], bf[2][4];
            #pragma unroll
            for (int mt = 0; mt < 4; mt++) {
                int r = mw * 64 + mt * 16 + (lane & 15);
                int c = sub * 16 + ((lane >> 4) << 3);
                ldsm4(af[mt], sA[cur] + r * 40 + c);
            }
            #pragma unroll
            for (int bt = 0; bt < 2; bt++) {
                int r = sub * 16 + (lane & 15);
                int c = nw * 32 + bt * 16 + ((lane >> 4) << 3);
                ldsm4t(bf[bt], sB[cur] + r * 264 + c);
            }
            #pragma unroll
            for (int mt = 0; mt < 4; mt++)
                #pragma unroll
                for (int nt = 0; nt < 4; nt++)
                    mma16816h(acc[mt][nt], af[mt], &bf[nt >> 1][(nt & 1) * 2]);
        }
        __syncthreads();
    }

    // ---------------- epilogue: bias + LayerNorm -----------------------------
    float* red   = (float*)sm;
    float* sred  = red;            // [128][8]
    float* s2red = red + 1024;     // [128][8]
    float* mus   = red + 2048;     // [128]
    float* rst   = red + 2176;     // [128]

    float bo[4][2];
    #pragma unroll
    for (int nt = 0; nt < 4; nt++) {
        int c = nw * 32 + nt * 8 + ((lane & 3) << 1);
        float2 bv = *(const float2*)(bout + c);
        bo[nt][0] = bv.x; bo[nt][1] = bv.y;
    }

    #pragma unroll
    for (int mt = 0; mt < 4; mt++)
        #pragma unroll
        for (int half = 0; half < 2; half++) {
            float s = 0.f, s2 = 0.f;
            #pragma unroll
            for (int nt = 0; nt < 4; nt++) {
                float v0 = acc[mt][nt][half * 2 + 0] + bo[nt][0];
                float v1 = acc[mt][nt][half * 2 + 1] + bo[nt][1];
                s += v0 + v1; s2 += v0 * v0 + v1 * v1;
            }
            s  += __shfl_xor_sync(0xffffffffu, s, 1);
            s  += __shfl_xor_sync(0xffffffffu, s, 2);
            s2 += __shfl_xor_sync(0xffffffffu, s2, 1);
            s2 += __shfl_xor_sync(0xffffffffu, s2, 2);
            if ((lane & 3) == 0) {
                int rl = mw * 64 + mt * 16 + (lane >> 2) + half * 8;
                sred[rl * 8 + nw] = s;
                s2red[rl * 8 + nw] = s2;
            }
        }
    __syncthreads();
    if (tid < 128) {
        float s = 0.f, s2 = 0.f;
        #pragma unroll
        for (int w = 0; w < 8; w++) { s += sred[tid * 8 + w]; s2 += s2red[tid * 8 + w]; }
        float mu = s * (1.f / 256.f);
        float var = s2 * (1.f / 256.f) - mu * mu;
        mus[tid] = mu;
        rst[tid] = rsqrtf(var + LN_EPS);
    }
    __syncthreads();

    #pragma unroll
    for (int mt = 0; mt < 4; mt++)
        #pragma unroll
        for (int half = 0; half < 2; half++) {
            int rl = mw * 64 + mt * 16 + (lane >> 2) + half * 8;
            float mu = mus[rl], rs = rst[rl];
            size_t orow = ((size_t)b * 8192 + (size_t)h * 1024 + t0 + rl) * 256;
            #pragma unroll
            for (int nt = 0; nt < 4; nt++) {
                int c = nw * 32 + nt * 8 + ((lane & 3) << 1);
                float2 g = *(const float2*)(gamma + c);
                float2 be = *(const float2*)(beta + c);
                float v0 = acc[mt][nt][half * 2 + 0] + bo[nt][0];
                float v1 = acc[mt][nt][half * 2 + 1] + bo[nt][1];
                float2 o = make_float2((v0 - mu) * rs * g.x + be.x,
                                       (v1 - mu) * rs * g.y + be.y);
                *(float2*)(out + orow + c) = o;
            }
        }
}

// ============================================================================
extern "C" void kernel_launch(void* const* d_in, const int* in_sizes, int n_in,
                              void* d_out, int out_size) {
    const float* x     = (const float*)d_in[0];
    const float* Wqkv  = (const float*)d_in[1];
    const float* Wout  = (const float*)d_in[2];
    const float* bout  = (const float*)d_in[3];
    const float* gamma = (const float*)d_in[4];
    const float* beta  = (const float*)d_in[5];
    float* out = (float*)d_out;

    const int statsSmem = 8 * 2560 * 2 + 8 * 1024 * 4;
    cudaFuncSetAttribute(k1_gemm, cudaFuncAttributeMaxDynamicSharedMemorySize, 3 * K1_STG * 2);
    cudaFuncSetAttribute(k_stats, cudaFuncAttributeMaxDynamicSharedMemorySize, statsSmem);
    cudaFuncSetAttribute(k4_out,  cudaFuncAttributeMaxDynamicSharedMemorySize, 3 * K4_STG * 2);

    k_cvt_x<<<16384, 256>>>(x);
    k_cvt_w<<<768, 256>>>(Wqkv);
    k1_gemm<<<dim3(6, 512), 256, 3 * K1_STG * 2>>>();
    k_stats<<<dim3(64, NSEG), 256, statsSmem>>>();
    k_cw<<<64, 256>>>(Wout);
    k4_out<<<dim3(8, 64), 512, 3 * K4_STG * 2>>>(bout, gamma, beta, out);
}